// round 3
// baseline (speedup 1.0000x reference)
#include <cuda_runtime.h>
#include <math.h>

// ---------------- problem constants ----------------
#define BB 4
#define TT 2048
#define DD 1024
#define HH 16
#define PP 64
#define FFD 4096
#define ROWS (BB*TT)          // 8192

// ---------------- scratch (static __device__, no allocation) ----------------
static __device__ float g_wqkv[DD * 3 * DD];        // packed [D, 3*D]  (Q|K|V cols)
static __device__ float g_nx  [ROWS * DD];          // layernorm1 out
static __device__ float g_qkv [ROWS * 3 * DD];      // [row, 3*D]
static __device__ float g_nv  [ROWS * DD];          // attention output (new_values)
static __device__ float g_ss  [ROWS * DD];          // seq_summary
static __device__ float g_pre [ROWS * DD];          // pre_ff
static __device__ float g_hid [ROWS * FFD];         // ff hidden

// ---------------- pack WQ/WK/WV into [D, 3D] ----------------
__global__ void pack_wqkv_kernel(const float* __restrict__ WQ,
                                 const float* __restrict__ WK,
                                 const float* __restrict__ WV) {
    long long idx = (long long)blockIdx.x * blockDim.x + threadIdx.x;
    long long total = (long long)DD * 3 * DD;
    if (idx >= total) return;
    int d = (int)(idx / (3 * DD));
    int c = (int)(idx % (3 * DD));
    int sel = c / DD;
    int hc  = c % DD;
    int h = hc / PP;
    int p = hc % PP;
    const float* W = (sel == 0) ? WQ : (sel == 1) ? WK : WV;
    g_wqkv[idx] = W[((long long)h * DD + d) * PP + p];
}

// ---------------- layernorm (optional residual add of X) ----------------
__global__ void ln_kernel(const float* __restrict__ x,
                          const float* __restrict__ gamma,
                          const float* __restrict__ beta,
                          const float* __restrict__ residual,  // may be null
                          float* __restrict__ out) {
    int row = blockIdx.x;
    const float* xr = x + (long long)row * DD;
    float* orow = out + (long long)row * DD;
    int tid = threadIdx.x;               // 256 threads, 4 elems each
    float v[4];
    float s = 0.f, sq = 0.f;
#pragma unroll
    for (int i = 0; i < 4; i++) {
        v[i] = xr[tid + i * 256];
        s += v[i];
        sq += v[i] * v[i];
    }
    // block reduce
    __shared__ float red[2][32];
    for (int o = 16; o > 0; o >>= 1) {
        s  += __shfl_xor_sync(0xffffffff, s, o);
        sq += __shfl_xor_sync(0xffffffff, sq, o);
    }
    int wid = tid >> 5, lid = tid & 31;
    if (lid == 0) { red[0][wid] = s; red[1][wid] = sq; }
    __syncthreads();
    if (wid == 0) {
        s = red[0][lid & 7]; sq = red[1][lid & 7];
        for (int o = 4; o > 0; o >>= 1) {
            s  += __shfl_xor_sync(0xffffffff, s, o);
            sq += __shfl_xor_sync(0xffffffff, sq, o);
        }
        if (lid == 0) { red[0][0] = s; red[1][0] = sq; }
    }
    __syncthreads();
    float mean = red[0][0] * (1.0f / DD);
    float var  = red[1][0] * (1.0f / DD) - mean * mean;
    float rstd = rsqrtf(var + 1e-5f);
#pragma unroll
    for (int i = 0; i < 4; i++) {
        int c = tid + i * 256;
        float o = (v[i] - mean) * rstd * gamma[c] + beta[c];
        if (residual) o += residual[(long long)row * DD + c];
        orow[c] = o;
    }
}

// ---------------- softmax over last dim (rows of length TT) ----------------
__global__ void softmax_kernel(float* __restrict__ a) {
    long long row = blockIdx.x;
    float* r = a + row * (long long)TT;
    int tid = threadIdx.x;               // 256 threads, 8 elems each
    float v[8];
    float mx = -1e30f;
#pragma unroll
    for (int i = 0; i < 8; i++) { v[i] = r[tid + i * 256]; mx = fmaxf(mx, v[i]); }
    __shared__ float red[32];
    for (int o = 16; o > 0; o >>= 1) mx = fmaxf(mx, __shfl_xor_sync(0xffffffff, mx, o));
    int wid = tid >> 5, lid = tid & 31;
    if (lid == 0) red[wid] = mx;
    __syncthreads();
    if (wid == 0) {
        mx = red[lid & 7];
        for (int o = 4; o > 0; o >>= 1) mx = fmaxf(mx, __shfl_xor_sync(0xffffffff, mx, o));
        if (lid == 0) red[0] = mx;
    }
    __syncthreads();
    mx = red[0];
    float s = 0.f;
#pragma unroll
    for (int i = 0; i < 8; i++) { v[i] = __expf(v[i] - mx); s += v[i]; }
    __syncthreads();
    for (int o = 16; o > 0; o >>= 1) s += __shfl_xor_sync(0xffffffff, s, o);
    if (lid == 0) red[wid] = s;
    __syncthreads();
    if (wid == 0) {
        s = red[lid & 7];
        for (int o = 4; o > 0; o >>= 1) s += __shfl_xor_sync(0xffffffff, s, o);
        if (lid == 0) red[0] = s;
    }
    __syncthreads();
    float inv = 1.0f / red[0];
#pragma unroll
    for (int i = 0; i < 8; i++) r[tid + i * 256] = v[i] * inv;
}

// ---------------- generic tiled fp32 GEMM ----------------
// C[M,N] = alpha * A @ B  (+bias) (gelu) (+residual)
// transB: B element (k,n) = B[n*ldb + k]
// batch: z -> b = z / hdiv, h = z % hdiv; offsets = b*strideXb + h*strideXh
#define Bb 64
#define Bn 64
#define Bk 16
__global__ void gemm_kernel(const float* __restrict__ A,
                            const float* __restrict__ B,
                            float* __restrict__ C,
                            int M, int N, int K,
                            int lda, int ldb, int ldc,
                            float alpha,
                            const float* __restrict__ bias,
                            const float* __restrict__ residual, int ldres,
                            int transB, int doGelu,
                            int hdiv,
                            long long sAb, long long sAh,
                            long long sBb, long long sBh,
                            long long sCb, long long sCh) {
    int z = blockIdx.z;
    int bb = z / hdiv, hh = z % hdiv;
    A += bb * sAb + hh * sAh;
    B += bb * sBb + hh * sBh;
    C += bb * sCb + hh * sCh;

    int row0 = blockIdx.y * Bb;
    int col0 = blockIdx.x * Bn;
    int tid = threadIdx.x;             // 256
    int tx = tid & 15, ty = tid >> 4;

    __shared__ float As[Bk][BB ? 68 : 68];
    __shared__ float Bs[Bk][68];

    float acc[4][4];
#pragma unroll
    for (int i = 0; i < 4; i++)
#pragma unroll
        for (int j = 0; j < 4; j++) acc[i][j] = 0.f;

    for (int k0 = 0; k0 < K; k0 += Bk) {
        // load A tile (64 rows x 16 k)
#pragma unroll
        for (int l = 0; l < 4; l++) {
            int i = tid + l * 256;
            int mm = i >> 4, kk = i & 15;
            As[kk][mm] = A[(long long)(row0 + mm) * lda + (k0 + kk)];
        }
        // load B tile (16 k x 64 cols)
        if (!transB) {
#pragma unroll
            for (int l = 0; l < 4; l++) {
                int i = tid + l * 256;
                int kk = i >> 6, nn = i & 63;
                Bs[kk][nn] = B[(long long)(k0 + kk) * ldb + (col0 + nn)];
            }
        } else {
#pragma unroll
            for (int l = 0; l < 4; l++) {
                int i = tid + l * 256;
                int nn = i >> 4, kk = i & 15;
                Bs[kk][nn] = B[(long long)(col0 + nn) * ldb + (k0 + kk)];
            }
        }
        __syncthreads();
#pragma unroll
        for (int kk = 0; kk < Bk; kk++) {
            float4 av = *(const float4*)&As[kk][ty * 4];
            float4 bv = *(const float4*)&Bs[kk][tx * 4];
            float a[4] = {av.x, av.y, av.z, av.w};
            float b[4] = {bv.x, bv.y, bv.z, bv.w};
#pragma unroll
            for (int i = 0; i < 4; i++)
#pragma unroll
                for (int j = 0; j < 4; j++) acc[i][j] = fmaf(a[i], b[j], acc[i][j]);
        }
        __syncthreads();
    }

#pragma unroll
    for (int i = 0; i < 4; i++) {
        int r = row0 + ty * 4 + i;
#pragma unroll
        for (int j = 0; j < 4; j++) {
            int c = col0 + tx * 4 + j;
            float v = acc[i][j] * alpha;
            if (bias) v += bias[c];
            if (doGelu) v = 0.5f * v * (1.0f + erff(v * 0.70710678118654752f));
            if (residual) v += residual[(long long)r * ldres + c];
            C[(long long)r * ldc + c] = v;
        }
    }
}

static void launch_gemm(const float* A, const float* B, float* C,
                        int M, int N, int K, int lda, int ldb, int ldc,
                        float alpha, const float* bias,
                        const float* residual, int ldres,
                        int transB, int doGelu,
                        int batch, int hdiv,
                        long long sAb, long long sAh,
                        long long sBb, long long sBh,
                        long long sCb, long long sCh) {
    dim3 grid(N / Bn, M / BB ? M / 64 : 1, batch);
    grid.y = M / 64;
    gemm_kernel<<<grid, 256>>>(A, B, C, M, N, K, lda, ldb, ldc, alpha,
                               bias, residual, ldres, transB, doGelu,
                               hdiv, sAb, sAh, sBb, sBh, sCb, sCh);
}

extern "C" void kernel_launch(void* const* d_in, const int* in_sizes, int n_in,
                              void* d_out, int out_size) {
    const float* X      = (const float*)d_in[0];
    const float* WQ     = (const float*)d_in[1];
    const float* WK     = (const float*)d_in[2];
    const float* WV     = (const float*)d_in[3];
    const float* WO     = (const float*)d_in[4];
    const float* attn_g = (const float*)d_in[5];
    const float* attn_b = (const float*)d_in[6];
    const float* ff_g   = (const float*)d_in[7];
    const float* ff_b   = (const float*)d_in[8];
    const float* fW1    = (const float*)d_in[9];
    const float* fb1    = (const float*)d_in[10];
    const float* fW2    = (const float*)d_in[11];
    const float* fb2    = (const float*)d_in[12];

    float* out0 = (float*)d_out;                         // [B,T,D]
    float* attn = out0 + (long long)ROWS * DD;           // [B,H,T,T]

    float *wqkv, *nx, *qkv, *nv, *ss, *pre, *hid;
    cudaGetSymbolAddress((void**)&wqkv, g_wqkv);
    cudaGetSymbolAddress((void**)&nx,   g_nx);
    cudaGetSymbolAddress((void**)&qkv,  g_qkv);
    cudaGetSymbolAddress((void**)&nv,   g_nv);
    cudaGetSymbolAddress((void**)&ss,   g_ss);
    cudaGetSymbolAddress((void**)&pre,  g_pre);
    cudaGetSymbolAddress((void**)&hid,  g_hid);

    // 1. pack weights
    {
        long long total = (long long)DD * 3 * DD;
        pack_wqkv_kernel<<<(unsigned)((total + 255) / 256), 256>>>(WQ, WK, WV);
    }
    // 2. layernorm1
    ln_kernel<<<ROWS, 256>>>(X, attn_g, attn_b, nullptr, nx);
    // 3. QKV gemm: [8192,1024] @ [1024,3072]
    launch_gemm(nx, wqkv, qkv, ROWS, 3 * DD, DD, DD, 3 * DD, 3 * DD,
                1.f, nullptr, nullptr, 0, 0, 0,
                1, 1, 0, 0, 0, 0, 0, 0);
    // 4. scores: per (b,h): rows=K-tokens, cols=Q-tokens (faithful index swap)
    //    A = K_bh [T,P], B^T = Q_bh, C = attn region
    launch_gemm(qkv + DD /* K block */, qkv /* Q block */, attn,
                TT, TT, PP, 3 * DD, 3 * DD, TT,
                0.125f /*1/sqrt(64)*/, nullptr, nullptr, 0,
                1 /*transB*/, 0,
                BB * HH, HH,
                (long long)TT * 3 * DD, PP,
                (long long)TT * 3 * DD, PP,
                (long long)HH * TT * TT, (long long)TT * TT);
    // 5. softmax over last dim, in place on attn output
    softmax_kernel<<<BB * HH * TT, 256>>>(attn);
    // 6. AV: per (b,h): [T,T] @ [T,P] -> nv[b,t,h*P+p]
    launch_gemm(attn, qkv + 2 * DD /* V block */, nv,
                TT, PP, TT, TT, 3 * DD, DD,
                1.f, nullptr, nullptr, 0, 0, 0,
                BB * HH, HH,
                (long long)HH * TT * TT, (long long)TT * TT,
                (long long)TT * 3 * DD, PP,
                (long long)TT * DD, PP);
    // 7. WO: [8192,1024] @ [1024,1024] (WO is already [H*P, D] row-major)
    launch_gemm(nv, WO, ss, ROWS, DD, DD, DD, DD, DD,
                1.f, nullptr, nullptr, 0, 0, 0,
                1, 1, 0, 0, 0, 0, 0, 0);
    // 8. pre_ff = X + LN(ss)
    ln_kernel<<<ROWS, 256>>>(ss, ff_g, ff_b, X, pre);
    // 9. FF1 + bias + exact gelu
    launch_gemm(pre, fW1, hid, ROWS, FFD, DD, DD, FFD, FFD,
                1.f, fb1, nullptr, 0, 0, 1,
                1, 1, 0, 0, 0, 0, 0, 0);
    // 10. FF2 + bias + residual(pre_ff) -> out0
    launch_gemm(hid, fW2, out0, ROWS, DD, FFD, FFD, DD, DD,
                1.f, fb2, pre, DD, 0, 0,
                1, 1, 0, 0, 0, 0, 0, 0);
}

// round 4
// speedup vs baseline: 1.5279x; 1.5279x over previous
#include <cuda_runtime.h>
#include <math.h>

// ---------------- problem constants ----------------
#define BB 4
#define TT 2048
#define DD 1024
#define HH 16
#define PP 64
#define FFD 4096
#define ROWS (BB*TT)          // 8192

// ---------------- scratch (static __device__, no allocation) ----------------
static __device__ float g_wqkv[DD * 3 * DD];        // packed [D, 3*D]  (Q|K|V cols)
static __device__ float g_nx  [ROWS * DD];          // layernorm1 out
static __device__ float g_qkv [ROWS * 3 * DD];      // [row, 3*D]
static __device__ float g_nv  [ROWS * DD];          // attention output (new_values)
static __device__ float g_ss  [ROWS * DD];          // seq_summary
static __device__ float g_pre [ROWS * DD];          // pre_ff
static __device__ float g_hid [ROWS * FFD];         // ff hidden

// ---------------- pack WQ/WK/WV into [D, 3D] ----------------
__global__ void pack_wqkv_kernel(const float* __restrict__ WQ,
                                 const float* __restrict__ WK,
                                 const float* __restrict__ WV) {
    long long idx = (long long)blockIdx.x * blockDim.x + threadIdx.x;
    long long total = (long long)DD * 3 * DD;
    if (idx >= total) return;
    int d = (int)(idx / (3 * DD));
    int c = (int)(idx % (3 * DD));
    int sel = c / DD;
    int hc  = c % DD;
    int h = hc / PP;
    int p = hc % PP;
    const float* W = (sel == 0) ? WQ : (sel == 1) ? WK : WV;
    g_wqkv[idx] = W[((long long)h * DD + d) * PP + p];
}

// ---------------- layernorm (optional residual add of X) ----------------
__global__ void ln_kernel(const float* __restrict__ x,
                          const float* __restrict__ gamma,
                          const float* __restrict__ beta,
                          const float* __restrict__ residual,  // may be null
                          float* __restrict__ out) {
    int row = blockIdx.x;
    const float* xr = x + (long long)row * DD;
    float* orow = out + (long long)row * DD;
    int tid = threadIdx.x;               // 256 threads, 4 elems each
    float v[4];
    float s = 0.f, sq = 0.f;
#pragma unroll
    for (int i = 0; i < 4; i++) {
        v[i] = xr[tid + i * 256];
        s += v[i];
        sq += v[i] * v[i];
    }
    __shared__ float red[2][32];
    for (int o = 16; o > 0; o >>= 1) {
        s  += __shfl_xor_sync(0xffffffff, s, o);
        sq += __shfl_xor_sync(0xffffffff, sq, o);
    }
    int wid = tid >> 5, lid = tid & 31;
    if (lid == 0) { red[0][wid] = s; red[1][wid] = sq; }
    __syncthreads();
    if (wid == 0) {
        s = red[0][lid & 7]; sq = red[1][lid & 7];
        for (int o = 4; o > 0; o >>= 1) {
            s  += __shfl_xor_sync(0xffffffff, s, o);
            sq += __shfl_xor_sync(0xffffffff, sq, o);
        }
        if (lid == 0) { red[0][0] = s; red[1][0] = sq; }
    }
    __syncthreads();
    float mean = red[0][0] * (1.0f / DD);
    float var  = red[1][0] * (1.0f / DD) - mean * mean;
    float rstd = rsqrtf(var + 1e-5f);
#pragma unroll
    for (int i = 0; i < 4; i++) {
        int c = tid + i * 256;
        float o = (v[i] - mean) * rstd * gamma[c] + beta[c];
        if (residual) o += residual[(long long)row * DD + c];
        orow[c] = o;
    }
}

// ---------------- softmax over last dim (rows of length TT) ----------------
__global__ void softmax_kernel(float* __restrict__ a) {
    long long row = blockIdx.x;
    float* r = a + row * (long long)TT;
    int tid = threadIdx.x;               // 256 threads, 8 elems each
    float v[8];
    float mx = -1e30f;
#pragma unroll
    for (int i = 0; i < 8; i++) { v[i] = r[tid + i * 256]; mx = fmaxf(mx, v[i]); }
    __shared__ float red[32];
    for (int o = 16; o > 0; o >>= 1) mx = fmaxf(mx, __shfl_xor_sync(0xffffffff, mx, o));
    int wid = tid >> 5, lid = tid & 31;
    if (lid == 0) red[wid] = mx;
    __syncthreads();
    if (wid == 0) {
        mx = red[lid & 7];
        for (int o = 4; o > 0; o >>= 1) mx = fmaxf(mx, __shfl_xor_sync(0xffffffff, mx, o));
        if (lid == 0) red[0] = mx;
    }
    __syncthreads();
    mx = red[0];
    float s = 0.f;
#pragma unroll
    for (int i = 0; i < 8; i++) { v[i] = __expf(v[i] - mx); s += v[i]; }
    __syncthreads();
    for (int o = 16; o > 0; o >>= 1) s += __shfl_xor_sync(0xffffffff, s, o);
    if (lid == 0) red[wid] = s;
    __syncthreads();
    if (wid == 0) {
        s = red[lid & 7];
        for (int o = 4; o > 0; o >>= 1) s += __shfl_xor_sync(0xffffffff, s, o);
        if (lid == 0) red[0] = s;
    }
    __syncthreads();
    float inv = 1.0f / red[0];
#pragma unroll
    for (int i = 0; i < 8; i++) r[tid + i * 256] = v[i] * inv;
}

// =====================================================================
// Double-buffered 128xBN x16 fp32 GEMM.
// 256 threads. Warp grid 4x2 (warp tile 32 x BN/2). Lane grid 4x8
// (thread tile 8 x TN, TN = BN/16). Vectorized float4 global loads
// staged through registers; prefetch next K-slice during compute.
// C = alpha*A@B (+bias)(gelu)(+residual). transB: B(k,n)=B[n*ldb+k].
// =====================================================================
template<int BN, int TN>
__global__ __launch_bounds__(256, 2)
void gemm_tpl(const float* __restrict__ A,
              const float* __restrict__ B,
              float* __restrict__ C,
              int M, int N, int K,
              int lda, int ldb, int ldc,
              float alpha,
              const float* __restrict__ bias,
              const float* __restrict__ residual, int ldres,
              int transB, int doGelu,
              int hdiv,
              long long sAb, long long sAh,
              long long sBb, long long sBh,
              long long sCb, long long sCh) {
    constexpr int BM = 128;
    constexpr int BK = 16;
    constexpr int TM = 8;
    constexpr int BF4 = (BK * BN) / (4 * 256);   // float4 B-loads per thread (2 or 1)

    int z = blockIdx.z;
    int bb = z / hdiv, hh = z % hdiv;
    A += bb * sAb + hh * sAh;
    B += bb * sBb + hh * sBh;
    C += bb * sCb + hh * sCh;

    const int row0 = blockIdx.y * BM;
    const int col0 = blockIdx.x * BN;
    const int tid  = threadIdx.x;
    const int warp = tid >> 5, lane = tid & 31;
    const int wm = warp & 3, wn = warp >> 2;      // 4 x 2 warps
    const int lm = lane & 3, ln = lane >> 2;      // 4 x 8 lanes
    const int tm0 = wm * 32 + lm * TM;            // thread row within tile
    const int tn0 = wn * (BN / 2) + ln * TN;      // thread col within tile

    __shared__ float As[2][BK][BM + 4];
    __shared__ float Bs[2][BK][BN + 4];

    float acc[TM][TN];
#pragma unroll
    for (int i = 0; i < TM; i++)
#pragma unroll
        for (int j = 0; j < TN; j++) acc[i][j] = 0.f;

    // A staging: 128x16 tile = 512 float4, 2 per thread (vector along k)
    const int a_row = tid >> 2;           // 0..63 (+64 for second load)
    const int a_kq  = (tid & 3) * 4;      // k offset 0,4,8,12
    float4 ar[2];

    // B staging (non-trans): idx -> kk = idx/(BN/4), nq = idx%(BN/4)
    // B staging (trans):     idx -> n = idx/4, kq = (idx%4)*4
    float4 br[BF4];

    // ---- load/store helpers ----
    auto loadA = [&](int k0) {
#pragma unroll
        for (int l = 0; l < 2; l++) {
            int r = a_row + l * 64;
            ar[l] = *(const float4*)&A[(long long)(row0 + r) * lda + (k0 + a_kq)];
        }
    };
    auto storeA = [&](int buf) {
#pragma unroll
        for (int l = 0; l < 2; l++) {
            int r = a_row + l * 64;
            As[buf][a_kq + 0][r] = ar[l].x;
            As[buf][a_kq + 1][r] = ar[l].y;
            As[buf][a_kq + 2][r] = ar[l].z;
            As[buf][a_kq + 3][r] = ar[l].w;
        }
    };
    auto loadB = [&](int k0) {
        if (!transB) {
#pragma unroll
            for (int l = 0; l < BF4; l++) {
                int idx = tid + l * 256;
                int kk = idx / (BN / 4);
                int nq = idx % (BN / 4);
                br[l] = *(const float4*)&B[(long long)(k0 + kk) * ldb + (col0 + nq * 4)];
            }
        } else {
#pragma unroll
            for (int l = 0; l < BF4; l++) {
                int idx = tid + l * 256;
                int n  = idx >> 2;
                int kq = (idx & 3) * 4;
                br[l] = *(const float4*)&B[(long long)(col0 + n) * ldb + (k0 + kq)];
            }
        }
    };
    auto storeB = [&](int buf) {
        if (!transB) {
#pragma unroll
            for (int l = 0; l < BF4; l++) {
                int idx = tid + l * 256;
                int kk = idx / (BN / 4);
                int nq = idx % (BN / 4);
                *(float4*)&Bs[buf][kk][nq * 4] = br[l];
            }
        } else {
#pragma unroll
            for (int l = 0; l < BF4; l++) {
                int idx = tid + l * 256;
                int n  = idx >> 2;
                int kq = (idx & 3) * 4;
                Bs[buf][kq + 0][n] = br[l].x;
                Bs[buf][kq + 1][n] = br[l].y;
                Bs[buf][kq + 2][n] = br[l].z;
                Bs[buf][kq + 3][n] = br[l].w;
            }
        }
    };

    // ---- prologue: fill buffer 0 ----
    loadA(0);
    loadB(0);
    storeA(0);
    storeB(0);

    int buf = 0;
    for (int k0 = 0; k0 < K; k0 += BK) {
        __syncthreads();
        const bool more = (k0 + BK) < K;
        if (more) { loadA(k0 + BK); loadB(k0 + BK); }

        // ---- compute on current buffer ----
#pragma unroll
        for (int kk = 0; kk < BK; kk++) {
            float af[TM], bf[TN];
            float4 a0 = *(const float4*)&As[buf][kk][tm0];
            float4 a1 = *(const float4*)&As[buf][kk][tm0 + 4];
            af[0] = a0.x; af[1] = a0.y; af[2] = a0.z; af[3] = a0.w;
            af[4] = a1.x; af[5] = a1.y; af[6] = a1.z; af[7] = a1.w;
#pragma unroll
            for (int j4 = 0; j4 < TN / 4; j4++) {
                float4 b0 = *(const float4*)&Bs[buf][kk][tn0 + j4 * 4];
                bf[j4 * 4 + 0] = b0.x; bf[j4 * 4 + 1] = b0.y;
                bf[j4 * 4 + 2] = b0.z; bf[j4 * 4 + 3] = b0.w;
            }
#pragma unroll
            for (int i = 0; i < TM; i++)
#pragma unroll
                for (int j = 0; j < TN; j++)
                    acc[i][j] = fmaf(af[i], bf[j], acc[i][j]);
        }

        if (more) {
            storeA(buf ^ 1);
            storeB(buf ^ 1);
            buf ^= 1;
        }
    }

    // ---- epilogue ----
#pragma unroll
    for (int i = 0; i < TM; i++) {
        int r = row0 + tm0 + i;
#pragma unroll
        for (int j4 = 0; j4 < TN / 4; j4++) {
            float4 v;
            float* vp = (float*)&v;
#pragma unroll
            for (int j = 0; j < 4; j++) {
                int c = col0 + tn0 + j4 * 4 + j;
                float x = acc[i][j4 * 4 + j] * alpha;
                if (bias) x += bias[c];
                if (doGelu) x = 0.5f * x * (1.0f + erff(x * 0.70710678118654752f));
                if (residual) x += residual[(long long)r * ldres + c];
                vp[j] = x;
            }
            *(float4*)&C[(long long)r * ldc + (col0 + tn0 + j4 * 4)] = v;
        }
    }
}

static void launch_gemm(const float* A, const float* B, float* C,
                        int M, int N, int K, int lda, int ldb, int ldc,
                        float alpha, const float* bias,
                        const float* residual, int ldres,
                        int transB, int doGelu,
                        int batch, int hdiv,
                        long long sAb, long long sAh,
                        long long sBb, long long sBh,
                        long long sCb, long long sCh) {
    if (N % 128 == 0) {
        dim3 grid(N / 128, M / 128, batch);
        gemm_tpl<128, 8><<<grid, 256>>>(A, B, C, M, N, K, lda, ldb, ldc, alpha,
                                        bias, residual, ldres, transB, doGelu,
                                        hdiv, sAb, sAh, sBb, sBh, sCb, sCh);
    } else {
        dim3 grid(N / 64, M / 128, batch);
        gemm_tpl<64, 4><<<grid, 256>>>(A, B, C, M, N, K, lda, ldb, ldc, alpha,
                                       bias, residual, ldres, transB, doGelu,
                                       hdiv, sAb, sAh, sBb, sBh, sCb, sCh);
    }
}

extern "C" void kernel_launch(void* const* d_in, const int* in_sizes, int n_in,
                              void* d_out, int out_size) {
    const float* X      = (const float*)d_in[0];
    const float* WQ     = (const float*)d_in[1];
    const float* WK     = (const float*)d_in[2];
    const float* WV     = (const float*)d_in[3];
    const float* WO     = (const float*)d_in[4];
    const float* attn_g = (const float*)d_in[5];
    const float* attn_b = (const float*)d_in[6];
    const float* ff_g   = (const float*)d_in[7];
    const float* ff_b   = (const float*)d_in[8];
    const float* fW1    = (const float*)d_in[9];
    const float* fb1    = (const float*)d_in[10];
    const float* fW2    = (const float*)d_in[11];
    const float* fb2    = (const float*)d_in[12];

    float* out0 = (float*)d_out;                         // [B,T,D]
    float* attn = out0 + (long long)ROWS * DD;           // [B,H,T,T]

    float *wqkv, *nx, *qkv, *nv, *ss, *pre, *hid;
    cudaGetSymbolAddress((void**)&wqkv, g_wqkv);
    cudaGetSymbolAddress((void**)&nx,   g_nx);
    cudaGetSymbolAddress((void**)&qkv,  g_qkv);
    cudaGetSymbolAddress((void**)&nv,   g_nv);
    cudaGetSymbolAddress((void**)&ss,   g_ss);
    cudaGetSymbolAddress((void**)&pre,  g_pre);
    cudaGetSymbolAddress((void**)&hid,  g_hid);

    // 1. pack weights
    {
        long long total = (long long)DD * 3 * DD;
        pack_wqkv_kernel<<<(unsigned)((total + 255) / 256), 256>>>(WQ, WK, WV);
    }
    // 2. layernorm1
    ln_kernel<<<ROWS, 256>>>(X, attn_g, attn_b, nullptr, nx);
    // 3. QKV gemm: [8192,1024] @ [1024,3072]
    launch_gemm(nx, wqkv, qkv, ROWS, 3 * DD, DD, DD, 3 * DD, 3 * DD,
                1.f, nullptr, nullptr, 0, 0, 0,
                1, 1, 0, 0, 0, 0, 0, 0);
    // 4. scores: per (b,h): rows=K-tokens, cols=Q-tokens (faithful index swap)
    launch_gemm(qkv + DD /* K block */, qkv /* Q block */, attn,
                TT, TT, PP, 3 * DD, 3 * DD, TT,
                0.125f, nullptr, nullptr, 0,
                1 /*transB*/, 0,
                BB * HH, HH,
                (long long)TT * 3 * DD, PP,
                (long long)TT * 3 * DD, PP,
                (long long)HH * TT * TT, (long long)TT * TT);
    // 5. softmax over last dim, in place
    softmax_kernel<<<BB * HH * TT, 256>>>(attn);
    // 6. AV: per (b,h): [T,T] @ [T,P] -> nv[b,t,h*P+p]   (N=64 tile)
    launch_gemm(attn, qkv + 2 * DD /* V block */, nv,
                TT, PP, TT, TT, 3 * DD, DD,
                1.f, nullptr, nullptr, 0, 0, 0,
                BB * HH, HH,
                (long long)HH * TT * TT, (long long)TT * TT,
                (long long)TT * 3 * DD, PP,
                (long long)TT * DD, PP);
    // 7. WO: [8192,1024] @ [1024,1024]
    launch_gemm(nv, WO, ss, ROWS, DD, DD, DD, DD, DD,
                1.f, nullptr, nullptr, 0, 0, 0,
                1, 1, 0, 0, 0, 0, 0, 0);
    // 8. pre_ff = X + LN(ss)
    ln_kernel<<<ROWS, 256>>>(ss, ff_g, ff_b, X, pre);
    // 9. FF1 + bias + exact gelu
    launch_gemm(pre, fW1, hid, ROWS, FFD, DD, DD, FFD, FFD,
                1.f, fb1, nullptr, 0, 0, 1,
                1, 1, 0, 0, 0, 0, 0, 0);
    // 10. FF2 + bias + residual(pre_ff) -> out0
    launch_gemm(hid, fW2, out0, ROWS, DD, FFD, FFD, DD, DD,
                1.f, fb2, pre, DD, 0, 0,
                1, 1, 0, 0, 0, 0, 0, 0);
}

// round 7
// speedup vs baseline: 4.9230x; 3.2221x over previous
#include <cuda_runtime.h>
#include <cuda_bf16.h>
#include <cstdint>
#include <math.h>

// ---------------- problem constants ----------------
#define BBATCH 4
#define TT 2048
#define DD 1024
#define HH 16
#define PP 64
#define FFD 4096
#define ROWS (BBATCH*TT)          // 8192

typedef __nv_bfloat16 bf16;

#define SMEM_SWIZZLE_128B(off) ((off) ^ (((off) >> 3) & 0x70))

__device__ __forceinline__ uint32_t smem_to_u32(const void* p) {
    uint32_t a;
    asm("{ .reg .u64 t; cvta.to.shared.u64 t, %1; cvt.u32.u64 %0, t; }" : "=r"(a) : "l"(p));
    return a;
}
__device__ __forceinline__ void cp16(uint32_t s, const void* g) {
    asm volatile("cp.async.cg.shared.global [%0], [%1], 16;" :: "r"(s), "l"(g));
}
#define CP_COMMIT() asm volatile("cp.async.commit_group;" ::: "memory")
#define CP_WAIT0()  asm volatile("cp.async.wait_group 0;" ::: "memory")
#define CP_WAIT1()  asm volatile("cp.async.wait_group 1;" ::: "memory")

__device__ __forceinline__ void ldsm_x4(uint32_t* r, uint32_t addr) {
    asm volatile("ldmatrix.sync.aligned.m8n8.x4.shared.b16 {%0,%1,%2,%3}, [%4];"
                 : "=r"(r[0]), "=r"(r[1]), "=r"(r[2]), "=r"(r[3]) : "r"(addr));
}
__device__ __forceinline__ void mma16816(float* c, const uint32_t* a, const uint32_t* b) {
    asm volatile("mma.sync.aligned.m16n8k16.row.col.f32.bf16.bf16.f32 "
                 "{%0,%1,%2,%3}, {%4,%5,%6,%7}, {%8,%9}, {%0,%1,%2,%3};"
                 : "+f"(c[0]), "+f"(c[1]), "+f"(c[2]), "+f"(c[3])
                 : "r"(a[0]), "r"(a[1]), "r"(a[2]), "r"(a[3]), "r"(b[0]), "r"(b[1]));
}

// ---------------- scratch (static __device__, no allocation) ----------------
static __device__ bf16 g_wqkvT_h[3 * DD * DD], g_wqkvT_l[3 * DD * DD];     // [3072,1024]
static __device__ bf16 g_woT_h[DD * DD],       g_woT_l[DD * DD];           // [1024,1024]
static __device__ bf16 g_fw1T_h[FFD * DD],     g_fw1T_l[FFD * DD];         // [4096,1024]
static __device__ bf16 g_fw2T_h[DD * FFD],     g_fw2T_l[DD * FFD];         // [1024,4096]
static __device__ bf16 g_nx_h[ROWS * DD],      g_nx_l[ROWS * DD];
static __device__ bf16 g_qkv_h[ROWS * 3 * DD], g_qkv_l[ROWS * 3 * DD];
static __device__ bf16 g_vt_h[(size_t)BBATCH * HH * PP * TT], g_vt_l[(size_t)BBATCH * HH * PP * TT];
static __device__ bf16 g_attn_h[(size_t)BBATCH * HH * TT * TT];
static __device__ bf16 g_attn_l[(size_t)BBATCH * HH * TT * TT];
static __device__ bf16 g_nv_h[ROWS * DD],      g_nv_l[ROWS * DD];
static __device__ bf16 g_pre_h[ROWS * DD],     g_pre_l[ROWS * DD];
static __device__ bf16 g_hid_h[(size_t)ROWS * FFD], g_hid_l[(size_t)ROWS * FFD];
static __device__ float g_ss [ROWS * DD];
static __device__ float g_pre[ROWS * DD];

// ---------------- transpose + split: fp32 in [R,C] -> bf16 hi/lo [C,R] ----------------
__global__ void transpose_split(const float* __restrict__ in,
                                bf16* __restrict__ ohi, bf16* __restrict__ olo,
                                int ldin, int ldout, long long sIn, long long sOut) {
    __shared__ float t[32][33];
    const float* ip = in + (long long)blockIdx.z * sIn;
    long long ob = (long long)blockIdx.z * sOut;
    int r0 = blockIdx.y * 32, c0 = blockIdx.x * 32;
    int tx = threadIdx.x, ty = threadIdx.y;
#pragma unroll
    for (int j = 0; j < 32; j += 8)
        t[ty + j][tx] = ip[(long long)(r0 + ty + j) * ldin + c0 + tx];
    __syncthreads();
#pragma unroll
    for (int j = 0; j < 32; j += 8) {
        float v = t[tx][ty + j];
        bf16 h = __float2bfloat16(v);
        long long o = ob + (long long)(c0 + ty + j) * ldout + r0 + tx;
        ohi[o] = h;
        olo[o] = __float2bfloat16(v - __bfloat162float(h));
    }
}

// ---------------- V^T extraction (bf16 -> bf16 transpose per head) ----------------
__global__ void vt_kernel(const bf16* __restrict__ qhi, const bf16* __restrict__ qlo,
                          bf16* __restrict__ vhi, bf16* __restrict__ vlo) {
    __shared__ bf16 th[32][33], tl[32][33];
    int z = blockIdx.z, bb = z >> 4, hh = z & 15;
    const long long ib = (long long)bb * TT * (3 * DD) + 2 * DD + hh * PP;
    const long long ob = (long long)z * PP * TT;
    int t0 = blockIdx.y * 32, p0 = blockIdx.x * 32;
    int tx = threadIdx.x, ty = threadIdx.y;
#pragma unroll
    for (int j = 0; j < 32; j += 8) {
        long long g = ib + (long long)(t0 + ty + j) * (3 * DD) + p0 + tx;
        th[ty + j][tx] = qhi[g];
        tl[ty + j][tx] = qlo[g];
    }
    __syncthreads();
#pragma unroll
    for (int j = 0; j < 32; j += 8) {
        long long o = ob + (long long)(p0 + ty + j) * TT + t0 + tx;
        vhi[o] = th[tx][ty + j];
        vlo[o] = tl[tx][ty + j];
    }
}

// ---------------- layernorm (+opt residual) -> optional fp32 + hi/lo bf16 ----------------
__global__ void ln_split_kernel(const float* __restrict__ x,
                                const float* __restrict__ gamma,
                                const float* __restrict__ beta,
                                const float* __restrict__ residual,
                                float* __restrict__ outf,
                                bf16* __restrict__ ohi, bf16* __restrict__ olo) {
    int row = blockIdx.x;
    const float* xr = x + (long long)row * DD;
    int tid = threadIdx.x;               // 256 threads, 4 elems each
    float v[4];
    float s = 0.f, sq = 0.f;
#pragma unroll
    for (int i = 0; i < 4; i++) {
        v[i] = xr[tid + i * 256];
        s += v[i]; sq += v[i] * v[i];
    }
    __shared__ float red[2][32];
    for (int o = 16; o > 0; o >>= 1) {
        s  += __shfl_xor_sync(0xffffffff, s, o);
        sq += __shfl_xor_sync(0xffffffff, sq, o);
    }
    int wid = tid >> 5, lid = tid & 31;
    if (lid == 0) { red[0][wid] = s; red[1][wid] = sq; }
    __syncthreads();
    if (wid == 0) {
        s = red[0][lid & 7]; sq = red[1][lid & 7];
        for (int o = 4; o > 0; o >>= 1) {
            s  += __shfl_xor_sync(0xffffffff, s, o);
            sq += __shfl_xor_sync(0xffffffff, sq, o);
        }
        if (lid == 0) { red[0][0] = s; red[1][0] = sq; }
    }
    __syncthreads();
    float mean = red[0][0] * (1.0f / DD);
    float var  = red[1][0] * (1.0f / DD) - mean * mean;
    float rstd = rsqrtf(var + 1e-5f);
    long long rb = (long long)row * DD;
#pragma unroll
    for (int i = 0; i < 4; i++) {
        int c = tid + i * 256;
        float o = (v[i] - mean) * rstd * gamma[c] + beta[c];
        if (residual) o += residual[rb + c];
        if (outf) outf[rb + c] = o;
        bf16 h = __float2bfloat16(o);
        ohi[rb + c] = h;
        olo[rb + c] = __float2bfloat16(o - __bfloat162float(h));
    }
}

// ---------------- softmax over last dim + split output ----------------
__global__ void softmax_split_kernel(float* __restrict__ a,
                                     bf16* __restrict__ ahi, bf16* __restrict__ alo) {
    long long row = blockIdx.x;
    float* r = a + row * (long long)TT;
    int tid = threadIdx.x;               // 256 threads, 8 elems each
    float v[8];
    float mx = -1e30f;
#pragma unroll
    for (int i = 0; i < 8; i++) { v[i] = r[tid + i * 256]; mx = fmaxf(mx, v[i]); }
    __shared__ float red[32];
    for (int o = 16; o > 0; o >>= 1) mx = fmaxf(mx, __shfl_xor_sync(0xffffffff, mx, o));
    int wid = tid >> 5, lid = tid & 31;
    if (lid == 0) red[wid] = mx;
    __syncthreads();
    if (wid == 0) {
        mx = red[lid & 7];
        for (int o = 4; o > 0; o >>= 1) mx = fmaxf(mx, __shfl_xor_sync(0xffffffff, mx, o));
        if (lid == 0) red[0] = mx;
    }
    __syncthreads();
    mx = red[0];
    float s = 0.f;
#pragma unroll
    for (int i = 0; i < 8; i++) { v[i] = __expf(v[i] - mx); s += v[i]; }
    __syncthreads();
    for (int o = 16; o > 0; o >>= 1) s += __shfl_xor_sync(0xffffffff, s, o);
    if (lid == 0) red[wid] = s;
    __syncthreads();
    if (wid == 0) {
        s = red[lid & 7];
        for (int o = 4; o > 0; o >>= 1) s += __shfl_xor_sync(0xffffffff, s, o);
        if (lid == 0) red[0] = s;
    }
    __syncthreads();
    float inv = 1.0f / red[0];
    long long rb = row * (long long)TT;
#pragma unroll
    for (int i = 0; i < 8; i++) {
        int idx = tid + i * 256;
        float val = v[i] * inv;
        r[idx] = val;
        bf16 h = __float2bfloat16(val);
        ahi[rb + idx] = h;
        alo[rb + idx] = __float2bfloat16(val - __bfloat162float(h));
    }
}

// =====================================================================
// Split-bf16 GEMM on mma.sync (HMMA).  C = alpha * A@B^T.
// A [M,K] hi/lo, B [N,K] hi/lo, both K-major bf16.
// Accumulates Ahi*Bhi + Alo*Bhi + Ahi*Blo in fp32 registers.
// 256 threads, tile 128 x BN, BK=64 elems; SW128-swizzled smem,
// cp.async double buffering, ldmatrix fragments (non-trans for both:
// [n][k]-stored B read non-trans yields the col-major B fragment).
// Fused epilogue: bias / GELU / residual; outputs fp32 and/or hi-lo bf16.
// =====================================================================
template<int BN>
__global__ __launch_bounds__(256, 1)
void gemm_mma(const bf16* __restrict__ Ahi, const bf16* __restrict__ Alo,
              const bf16* __restrict__ Bhi, const bf16* __restrict__ Blo,
              int K, int lda, int ldb, int ldc,
              float alpha,
              const float* __restrict__ bias,
              const float* __restrict__ residual, int ldres,
              int doGelu,
              float* __restrict__ Cf,
              bf16* __restrict__ Chi, bf16* __restrict__ Clo,
              int hdiv,
              long long sAb, long long sAh,
              long long sBb, long long sBh,
              long long sCb, long long sCh) {
    constexpr int TILE_A = 128 * 128;        // bytes (128 rows x 64 bf16)
    constexpr int TILE_B = BN * 128;
    constexpr int STAGE  = 2 * TILE_A + 2 * TILE_B;
    constexpr int WGM = (BN == 128) ? 2 : 4;     // warp grid
    constexpr int WGN = (BN == 128) ? 4 : 2;
    constexpr int MT  = (128 / WGM) / 16;        // m16 tiles per warp (4 or 2)
    constexpr int NT  = (BN / WGN) / 8;          // n8 tiles per warp (4)

    extern __shared__ char smem[];
    const uint32_t sb = smem_to_u32(smem);

    const int tid  = threadIdx.x;
    const int warp = tid >> 5, lane = tid & 31;
    const int wm = warp / WGN, wn = warp % WGN;
    const int rw = wm * (128 / WGM);
    const int cw = wn * (BN / WGN);

    int z = blockIdx.z;
    int bbz = z / hdiv, hhz = z % hdiv;
    Ahi += bbz * sAb + hhz * sAh;  Alo += bbz * sAb + hhz * sAh;
    Bhi += bbz * sBb + hhz * sBh;  Blo += bbz * sBb + hhz * sBh;
    const long long coff = bbz * sCb + hhz * sCh;

    const int row0 = blockIdx.y * 128;
    const int col0 = blockIdx.x * BN;

    float acc[MT][NT][4];
#pragma unroll
    for (int i = 0; i < MT; i++)
#pragma unroll
        for (int j = 0; j < NT; j++)
#pragma unroll
            for (int q = 0; q < 4; q++) acc[i][j][q] = 0.f;

    const int nc = K >> 6;

    auto copy_chunk = [&](int k0, int buf) {
        uint32_t ah = sb + buf * STAGE;
        uint32_t al = ah + TILE_A;
        uint32_t bh = ah + 2 * TILE_A;
        uint32_t bl = bh + TILE_B;
#pragma unroll
        for (int l = 0; l < 4; l++) {
            int idx = tid + l * 256;
            int row = idx >> 3, seg = idx & 7;
            long long g = (long long)(row0 + row) * lda + k0 + seg * 8;
            uint32_t sw = SMEM_SWIZZLE_128B((uint32_t)(row * 128 + seg * 16));
            cp16(ah + sw, Ahi + g);
            cp16(al + sw, Alo + g);
        }
#pragma unroll
        for (int l = 0; l < BN / 32; l++) {
            int idx = tid + l * 256;
            int row = idx >> 3, seg = idx & 7;
            long long g = (long long)(col0 + row) * ldb + k0 + seg * 8;
            uint32_t sw = SMEM_SWIZZLE_128B((uint32_t)(row * 128 + seg * 16));
            cp16(bh + sw, Bhi + g);
            cp16(bl + sw, Blo + g);
        }
    };

    copy_chunk(0, 0);
    CP_COMMIT();

    const int lr = lane & 15;       // A ldmatrix row
    const int lk = lane >> 4;       // A ldmatrix k-half
    const int bnrow = (lane & 7) + ((lane >> 4) & 1) * 8;   // B ldmatrix n row
    const int bkh   = (lane >> 3) & 1;                      // B ldmatrix k-half

    for (int c = 0; c < nc; c++) {
        if (c + 1 < nc) {
            copy_chunk((c + 1) << 6, (c + 1) & 1);
            CP_COMMIT();
            CP_WAIT1();
        } else {
            CP_WAIT0();
        }
        __syncthreads();

        uint32_t abase = sb + (c & 1) * STAGE;
        uint32_t bbase = abase + 2 * TILE_A;
#pragma unroll
        for (int ks = 0; ks < 4; ks++) {
            uint32_t afh[MT][4], afl[MT][4];
#pragma unroll
            for (int mt = 0; mt < MT; mt++) {
                uint32_t off = SMEM_SWIZZLE_128B((uint32_t)((rw + mt * 16 + lr) * 128 + ks * 32 + lk * 16));
                ldsm_x4(afh[mt], abase + off);
                ldsm_x4(afl[mt], abase + TILE_A + off);
            }
            uint32_t bfh[NT][2], bfl[NT][2];
#pragma unroll
            for (int g = 0; g < NT / 2; g++) {
                uint32_t off = SMEM_SWIZZLE_128B((uint32_t)((cw + g * 16 + bnrow) * 128 + ks * 32 + bkh * 16));
                uint32_t r4[4];
                ldsm_x4(r4, bbase + off);
                bfh[2 * g][0] = r4[0]; bfh[2 * g][1] = r4[1];
                bfh[2 * g + 1][0] = r4[2]; bfh[2 * g + 1][1] = r4[3];
                ldsm_x4(r4, bbase + TILE_B + off);
                bfl[2 * g][0] = r4[0]; bfl[2 * g][1] = r4[1];
                bfl[2 * g + 1][0] = r4[2]; bfl[2 * g + 1][1] = r4[3];
            }
#pragma unroll
            for (int mt = 0; mt < MT; mt++)
#pragma unroll
                for (int nt = 0; nt < NT; nt++) {
                    mma16816(acc[mt][nt], afh[mt], bfh[nt]);
                    mma16816(acc[mt][nt], afl[mt], bfh[nt]);
                    mma16816(acc[mt][nt], afh[mt], bfl[nt]);
                }
        }
        __syncthreads();
    }

    // ---- epilogue: regs -> smem stage -> fused ops -> coalesced gmem ----
    constexpr int SP = BN + 4;                 // stage pitch (floats)
    float* stage = (float*)smem;
    {
        int qr = lane >> 2;
        int qc = (lane & 3) * 2;
#pragma unroll
        for (int mt = 0; mt < MT; mt++) {
            int r1 = rw + mt * 16 + qr;
            int r2 = r1 + 8;
#pragma unroll
            for (int nt = 0; nt < NT; nt++) {
                int cc = cw + nt * 8 + qc;
                stage[r1 * SP + cc]     = acc[mt][nt][0];
                stage[r1 * SP + cc + 1] = acc[mt][nt][1];
                stage[r2 * SP + cc]     = acc[mt][nt][2];
                stage[r2 * SP + cc + 1] = acc[mt][nt][3];
            }
        }
    }
    __syncthreads();
#pragma unroll
    for (int l = 0; l < BN / 8; l++) {
        int idx = tid + l * 256;
        int r2 = idx / (BN / 4);
        int c4 = (idx % (BN / 4)) * 4;
        int grow = row0 + r2;
        int gcol = col0 + c4;
        float4 v = *(float4*)&stage[r2 * SP + c4];
        float* vp = (float*)&v;
#pragma unroll
        for (int j = 0; j < 4; j++) {
            float x = vp[j] * alpha;
            if (bias) x += bias[gcol + j];
            if (doGelu) x = 0.5f * x * (1.0f + erff(x * 0.70710678118654752f));
            if (residual) x += residual[(long long)grow * ldres + gcol + j];
            vp[j] = x;
        }
        long long o = coff + (long long)grow * ldc + gcol;
        if (Cf) *(float4*)&Cf[o] = v;
        if (Chi) {
            __nv_bfloat162 h01 = __floats2bfloat162_rn(vp[0], vp[1]);
            __nv_bfloat162 h23 = __floats2bfloat162_rn(vp[2], vp[3]);
            float2 f01 = __bfloat1622float2(h01);
            float2 f23 = __bfloat1622float2(h23);
            __nv_bfloat162 l01 = __floats2bfloat162_rn(vp[0] - f01.x, vp[1] - f01.y);
            __nv_bfloat162 l23 = __floats2bfloat162_rn(vp[2] - f23.x, vp[3] - f23.y);
            uint2 hv, lv;
            hv.x = *(uint32_t*)&h01; hv.y = *(uint32_t*)&h23;
            lv.x = *(uint32_t*)&l01; lv.y = *(uint32_t*)&l23;
            *(uint2*)&Chi[o] = hv;
            *(uint2*)&Clo[o] = lv;
        }
    }
}

// ---------------- host side ----------------
static const int SMEM128 = 2 * (2 * 128 * 128 + 2 * 128 * 128);   // 131072
static const int SMEM64  = 2 * (2 * 128 * 128 + 2 * 64 * 128);    // 98304

extern "C" void kernel_launch(void* const* d_in, const int* in_sizes, int n_in,
                              void* d_out, int out_size) {
    const float* X      = (const float*)d_in[0];
    const float* WQ     = (const float*)d_in[1];
    const float* WK     = (const float*)d_in[2];
    const float* WV     = (const float*)d_in[3];
    const float* WO     = (const float*)d_in[4];
    const float* attn_g = (const float*)d_in[5];
    const float* attn_b = (const float*)d_in[6];
    const float* ff_g   = (const float*)d_in[7];
    const float* ff_b   = (const float*)d_in[8];
    const float* fW1    = (const float*)d_in[9];
    const float* fb1    = (const float*)d_in[10];
    const float* fW2    = (const float*)d_in[11];
    const float* fb2    = (const float*)d_in[12];

    float* out0 = (float*)d_out;                         // [B,T,D]
    float* attn = out0 + (long long)ROWS * DD;           // [B,H,T,T]

    cudaFuncSetAttribute(gemm_mma<128>, cudaFuncAttributeMaxDynamicSharedMemorySize, SMEM128);
    cudaFuncSetAttribute(gemm_mma<64>,  cudaFuncAttributeMaxDynamicSharedMemorySize, SMEM64);

    bf16 *wqkvT_h, *wqkvT_l, *woT_h, *woT_l, *fw1T_h, *fw1T_l, *fw2T_h, *fw2T_l;
    bf16 *nx_h, *nx_l, *qkv_h, *qkv_l, *vt_h, *vt_l, *attn_h, *attn_l;
    bf16 *nv_h, *nv_l, *pre_h, *pre_l, *hid_h, *hid_l;
    float *ss, *pre;
    cudaGetSymbolAddress((void**)&wqkvT_h, g_wqkvT_h); cudaGetSymbolAddress((void**)&wqkvT_l, g_wqkvT_l);
    cudaGetSymbolAddress((void**)&woT_h,  g_woT_h);    cudaGetSymbolAddress((void**)&woT_l,  g_woT_l);
    cudaGetSymbolAddress((void**)&fw1T_h, g_fw1T_h);   cudaGetSymbolAddress((void**)&fw1T_l, g_fw1T_l);
    cudaGetSymbolAddress((void**)&fw2T_h, g_fw2T_h);   cudaGetSymbolAddress((void**)&fw2T_l, g_fw2T_l);
    cudaGetSymbolAddress((void**)&nx_h,   g_nx_h);     cudaGetSymbolAddress((void**)&nx_l,   g_nx_l);
    cudaGetSymbolAddress((void**)&qkv_h,  g_qkv_h);    cudaGetSymbolAddress((void**)&qkv_l,  g_qkv_l);
    cudaGetSymbolAddress((void**)&vt_h,   g_vt_h);     cudaGetSymbolAddress((void**)&vt_l,   g_vt_l);
    cudaGetSymbolAddress((void**)&attn_h, g_attn_h);   cudaGetSymbolAddress((void**)&attn_l, g_attn_l);
    cudaGetSymbolAddress((void**)&nv_h,   g_nv_h);     cudaGetSymbolAddress((void**)&nv_l,   g_nv_l);
    cudaGetSymbolAddress((void**)&pre_h,  g_pre_h);    cudaGetSymbolAddress((void**)&pre_l,  g_pre_l);
    cudaGetSymbolAddress((void**)&hid_h,  g_hid_h);    cudaGetSymbolAddress((void**)&hid_l,  g_hid_l);
    cudaGetSymbolAddress((void**)&ss,     g_ss);       cudaGetSymbolAddress((void**)&pre,    g_pre);

    dim3 tb32(32, 8);

    // 1. weight transposes + splits
    transpose_split<<<dim3(2, 32, 16), tb32>>>(WQ, wqkvT_h,                wqkvT_l,                64, DD, (long long)DD * PP, (long long)PP * DD);
    transpose_split<<<dim3(2, 32, 16), tb32>>>(WK, wqkvT_h + DD * DD,      wqkvT_l + DD * DD,      64, DD, (long long)DD * PP, (long long)PP * DD);
    transpose_split<<<dim3(2, 32, 16), tb32>>>(WV, wqkvT_h + 2 * DD * DD,  wqkvT_l + 2 * DD * DD,  64, DD, (long long)DD * PP, (long long)PP * DD);
    transpose_split<<<dim3(128, 32, 1), tb32>>>(fW1, fw1T_h, fw1T_l, FFD, DD, 0, 0);
    transpose_split<<<dim3(32, 128, 1), tb32>>>(fW2, fw2T_h, fw2T_l, DD, FFD, 0, 0);
    transpose_split<<<dim3(32, 32, 1),  tb32>>>(WO,  woT_h,  woT_l,  DD, DD, 0, 0);

    // 2. LN1 -> nx hi/lo
    ln_split_kernel<<<ROWS, 256>>>(X, attn_g, attn_b, nullptr, nullptr, nx_h, nx_l);

    // 3. QKV: [8192,1024] x [3072,1024]^T -> qkv hi/lo [8192,3072]
    gemm_mma<128><<<dim3(24, 64, 1), 256, SMEM128>>>(
        nx_h, nx_l, wqkvT_h, wqkvT_l, DD, DD, DD, 3 * DD,
        1.f, nullptr, nullptr, 0, 0, nullptr, qkv_h, qkv_l,
        1, 0, 0, 0, 0, 0, 0);

    // 4. V^T per head
    vt_kernel<<<dim3(2, 64, 64), tb32>>>(qkv_h, qkv_l, vt_h, vt_l);

    // 5. scores (faithful index swap): rows = K-tokens, cols = Q-tokens
    gemm_mma<128><<<dim3(16, 16, 64), 256, SMEM128>>>(
        qkv_h + DD, qkv_l + DD, qkv_h, qkv_l, PP, 3 * DD, 3 * DD, TT,
        0.125f, nullptr, nullptr, 0, 0, attn, nullptr, nullptr,
        16,
        (long long)TT * 3 * DD, PP,
        (long long)TT * 3 * DD, PP,
        16LL * TT * TT, (long long)TT * TT);

    // 6. softmax + split
    softmax_split_kernel<<<BBATCH * HH * TT, 256>>>(attn, attn_h, attn_l);

    // 7. AV: [T,T] x [P=64,T]^T -> nv hi/lo
    gemm_mma<64><<<dim3(1, 16, 64), 256, SMEM64>>>(
        attn_h, attn_l, vt_h, vt_l, TT, TT, TT, DD,
        1.f, nullptr, nullptr, 0, 0, nullptr, nv_h, nv_l,
        16,
        16LL * TT * TT, (long long)TT * TT,
        16LL * PP * TT, (long long)PP * TT,
        (long long)TT * DD, PP);

    // 8. WO: [8192,1024] x [1024,1024]^T -> ss fp32
    gemm_mma<128><<<dim3(8, 64, 1), 256, SMEM128>>>(
        nv_h, nv_l, woT_h, woT_l, DD, DD, DD, DD,
        1.f, nullptr, nullptr, 0, 0, ss, nullptr, nullptr,
        1, 0, 0, 0, 0, 0, 0);

    // 9. pre_ff = X + LN(ss): fp32 + hi/lo
    ln_split_kernel<<<ROWS, 256>>>(ss, ff_g, ff_b, X, pre, pre_h, pre_l);

    // 10. FF1 + bias + gelu -> hid hi/lo
    gemm_mma<128><<<dim3(32, 64, 1), 256, SMEM128>>>(
        pre_h, pre_l, fw1T_h, fw1T_l, DD, DD, DD, FFD,
        1.f, fb1, nullptr, 0, 1, nullptr, hid_h, hid_l,
        1, 0, 0, 0, 0, 0, 0);

    // 11. FF2 + bias + residual(pre) -> out0 fp32
    gemm_mma<128><<<dim3(8, 64, 1), 256, SMEM128>>>(
        hid_h, hid_l, fw2T_h, fw2T_l, FFD, FFD, FFD, DD,
        1.f, fb2, pre, DD, 0, out0, nullptr, nullptr,
        1, 0, 0, 0, 0, 0, 0);
}

// round 8
// speedup vs baseline: 5.4076x; 1.0984x over previous
#include <cuda_runtime.h>
#include <cuda_bf16.h>
#include <cstdint>
#include <math.h>

// ---------------- problem constants ----------------
#define BBATCH 4
#define TT 2048
#define DD 1024
#define HH 16
#define PP 64
#define FFD 4096
#define ROWS (BBATCH*TT)          // 8192

typedef __nv_bfloat16 bf16;

#define SMEM_SWIZZLE_128B(off) ((off) ^ (((off) >> 3) & 0x70))
#define SMEM_SWIZZLE_64B(off)  ((off) ^ (((off) >> 3) & 0x30))

__device__ __forceinline__ uint32_t smem_to_u32(const void* p) {
    uint32_t a;
    asm("{ .reg .u64 t; cvta.to.shared.u64 t, %1; cvt.u32.u64 %0, t; }" : "=r"(a) : "l"(p));
    return a;
}
__device__ __forceinline__ void cp16(uint32_t s, const void* g) {
    asm volatile("cp.async.cg.shared.global [%0], [%1], 16;" :: "r"(s), "l"(g));
}
#define CP_COMMIT() asm volatile("cp.async.commit_group;" ::: "memory")
#define CP_WAIT0()  asm volatile("cp.async.wait_group 0;" ::: "memory")
#define CP_WAIT1()  asm volatile("cp.async.wait_group 1;" ::: "memory")

__device__ __forceinline__ void ldsm_x4(uint32_t* r, uint32_t addr) {
    asm volatile("ldmatrix.sync.aligned.m8n8.x4.shared.b16 {%0,%1,%2,%3}, [%4];"
                 : "=r"(r[0]), "=r"(r[1]), "=r"(r[2]), "=r"(r[3]) : "r"(addr));
}
__device__ __forceinline__ void mma16816(float* c, const uint32_t* a, const uint32_t* b) {
    asm volatile("mma.sync.aligned.m16n8k16.row.col.f32.bf16.bf16.f32 "
                 "{%0,%1,%2,%3}, {%4,%5,%6,%7}, {%8,%9}, {%0,%1,%2,%3};"
                 : "+f"(c[0]), "+f"(c[1]), "+f"(c[2]), "+f"(c[3])
                 : "r"(a[0]), "r"(a[1]), "r"(a[2]), "r"(a[3]), "r"(b[0]), "r"(b[1]));
}

// ---------------- scratch (static __device__, no allocation) ----------------
static __device__ bf16 g_wqkvT_h[3 * DD * DD], g_wqkvT_l[3 * DD * DD];     // [3072,1024]
static __device__ bf16 g_woT_h[DD * DD],       g_woT_l[DD * DD];           // [1024,1024]
static __device__ bf16 g_fw1T_h[FFD * DD],     g_fw1T_l[FFD * DD];         // [4096,1024]
static __device__ bf16 g_fw2T_h[DD * FFD],     g_fw2T_l[DD * FFD];         // [1024,4096]
static __device__ bf16 g_nx_h[ROWS * DD],      g_nx_l[ROWS * DD];
static __device__ bf16 g_qkv_h[ROWS * 3 * DD], g_qkv_l[ROWS * 3 * DD];
static __device__ bf16 g_vt_h[(size_t)BBATCH * HH * PP * TT], g_vt_l[(size_t)BBATCH * HH * PP * TT];
static __device__ bf16 g_attn_h[(size_t)BBATCH * HH * TT * TT];
static __device__ bf16 g_attn_l[(size_t)BBATCH * HH * TT * TT];
static __device__ bf16 g_nv_h[ROWS * DD],      g_nv_l[ROWS * DD];
static __device__ bf16 g_pre_h[ROWS * DD],     g_pre_l[ROWS * DD];
static __device__ bf16 g_hid_h[(size_t)ROWS * FFD], g_hid_l[(size_t)ROWS * FFD];
static __device__ float g_ss [ROWS * DD];
static __device__ float g_pre[ROWS * DD];

// ---------------- transpose + split: fp32 in [R,C] -> bf16 hi/lo [C,R] ----------------
__global__ void transpose_split(const float* __restrict__ in,
                                bf16* __restrict__ ohi, bf16* __restrict__ olo,
                                int ldin, int ldout, long long sIn, long long sOut) {
    __shared__ float t[32][33];
    const float* ip = in + (long long)blockIdx.z * sIn;
    long long ob = (long long)blockIdx.z * sOut;
    int r0 = blockIdx.y * 32, c0 = blockIdx.x * 32;
    int tx = threadIdx.x, ty = threadIdx.y;
#pragma unroll
    for (int j = 0; j < 32; j += 8)
        t[ty + j][tx] = ip[(long long)(r0 + ty + j) * ldin + c0 + tx];
    __syncthreads();
#pragma unroll
    for (int j = 0; j < 32; j += 8) {
        float v = t[tx][ty + j];
        bf16 h = __float2bfloat16(v);
        long long o = ob + (long long)(c0 + ty + j) * ldout + r0 + tx;
        ohi[o] = h;
        olo[o] = __float2bfloat16(v - __bfloat162float(h));
    }
}

// ---------------- V^T extraction (bf16 -> bf16 transpose per head) ----------------
__global__ void vt_kernel(const bf16* __restrict__ qhi, const bf16* __restrict__ qlo,
                          bf16* __restrict__ vhi, bf16* __restrict__ vlo) {
    __shared__ bf16 th[32][33], tl[32][33];
    int z = blockIdx.z, bb = z >> 4, hh = z & 15;
    const long long ib = (long long)bb * TT * (3 * DD) + 2 * DD + hh * PP;
    const long long ob = (long long)z * PP * TT;
    int t0 = blockIdx.y * 32, p0 = blockIdx.x * 32;
    int tx = threadIdx.x, ty = threadIdx.y;
#pragma unroll
    for (int j = 0; j < 32; j += 8) {
        long long g = ib + (long long)(t0 + ty + j) * (3 * DD) + p0 + tx;
        th[ty + j][tx] = qhi[g];
        tl[ty + j][tx] = qlo[g];
    }
    __syncthreads();
#pragma unroll
    for (int j = 0; j < 32; j += 8) {
        long long o = ob + (long long)(p0 + ty + j) * TT + t0 + tx;
        vhi[o] = th[tx][ty + j];
        vlo[o] = tl[tx][ty + j];
    }
}

// ---------------- layernorm (+opt residual), float4 path ----------------
__global__ void ln_split_kernel(const float* __restrict__ x,
                                const float* __restrict__ gamma,
                                const float* __restrict__ beta,
                                const float* __restrict__ residual,
                                float* __restrict__ outf,
                                bf16* __restrict__ ohi, bf16* __restrict__ olo) {
    int row = blockIdx.x;
    int tid = threadIdx.x;               // 256 threads, 4 contiguous elems each
    long long rb = (long long)row * DD;
    float4 v = *(const float4*)(x + rb + tid * 4);
    float s  = v.x + v.y + v.z + v.w;
    float sq = v.x * v.x + v.y * v.y + v.z * v.z + v.w * v.w;
    __shared__ float red[2][32];
    for (int o = 16; o > 0; o >>= 1) {
        s  += __shfl_xor_sync(0xffffffff, s, o);
        sq += __shfl_xor_sync(0xffffffff, sq, o);
    }
    int wid = tid >> 5, lid = tid & 31;
    if (lid == 0) { red[0][wid] = s; red[1][wid] = sq; }
    __syncthreads();
    if (wid == 0) {
        s = red[0][lid & 7]; sq = red[1][lid & 7];
        for (int o = 4; o > 0; o >>= 1) {
            s  += __shfl_xor_sync(0xffffffff, s, o);
            sq += __shfl_xor_sync(0xffffffff, sq, o);
        }
        if (lid == 0) { red[0][0] = s; red[1][0] = sq; }
    }
    __syncthreads();
    float mean = red[0][0] * (1.0f / DD);
    float var  = red[1][0] * (1.0f / DD) - mean * mean;
    float rstd = rsqrtf(var + 1e-5f);
    float4 gm = *(const float4*)(gamma + tid * 4);
    float4 bt = *(const float4*)(beta  + tid * 4);
    float o0 = (v.x - mean) * rstd * gm.x + bt.x;
    float o1 = (v.y - mean) * rstd * gm.y + bt.y;
    float o2 = (v.z - mean) * rstd * gm.z + bt.z;
    float o3 = (v.w - mean) * rstd * gm.w + bt.w;
    if (residual) {
        float4 rr = *(const float4*)(residual + rb + tid * 4);
        o0 += rr.x; o1 += rr.y; o2 += rr.z; o3 += rr.w;
    }
    if (outf) {
        float4 ov = make_float4(o0, o1, o2, o3);
        *(float4*)(outf + rb + tid * 4) = ov;
    }
    __nv_bfloat162 h01 = __floats2bfloat162_rn(o0, o1);
    __nv_bfloat162 h23 = __floats2bfloat162_rn(o2, o3);
    float2 f01 = __bfloat1622float2(h01);
    float2 f23 = __bfloat1622float2(h23);
    __nv_bfloat162 l01 = __floats2bfloat162_rn(o0 - f01.x, o1 - f01.y);
    __nv_bfloat162 l23 = __floats2bfloat162_rn(o2 - f23.x, o3 - f23.y);
    uint2 hv, lv;
    hv.x = *(uint32_t*)&h01; hv.y = *(uint32_t*)&h23;
    lv.x = *(uint32_t*)&l01; lv.y = *(uint32_t*)&l23;
    *(uint2*)(ohi + rb + tid * 4) = hv;
    *(uint2*)(olo + rb + tid * 4) = lv;
}

// ---------------- softmax over last dim + split output (float4 path) ----------------
__global__ void softmax_split_kernel(float* __restrict__ a,
                                     bf16* __restrict__ ahi, bf16* __restrict__ alo) {
    long long row = blockIdx.x;
    float4* r4 = (float4*)(a + row * (long long)TT);
    int tid = threadIdx.x;               // 256 threads, 2 float4 each
    float4 va = r4[tid], vb = r4[tid + 256];
    float v[8] = {va.x, va.y, va.z, va.w, vb.x, vb.y, vb.z, vb.w};
    float mx = -1e30f;
#pragma unroll
    for (int i = 0; i < 8; i++) mx = fmaxf(mx, v[i]);
    __shared__ float red[32];
    for (int o = 16; o > 0; o >>= 1) mx = fmaxf(mx, __shfl_xor_sync(0xffffffff, mx, o));
    int wid = tid >> 5, lid = tid & 31;
    if (lid == 0) red[wid] = mx;
    __syncthreads();
    if (wid == 0) {
        mx = red[lid & 7];
        for (int o = 4; o > 0; o >>= 1) mx = fmaxf(mx, __shfl_xor_sync(0xffffffff, mx, o));
        if (lid == 0) red[0] = mx;
    }
    __syncthreads();
    mx = red[0];
    float s = 0.f;
#pragma unroll
    for (int i = 0; i < 8; i++) { v[i] = __expf(v[i] - mx); s += v[i]; }
    __syncthreads();
    for (int o = 16; o > 0; o >>= 1) s += __shfl_xor_sync(0xffffffff, s, o);
    if (lid == 0) red[wid] = s;
    __syncthreads();
    if (wid == 0) {
        s = red[lid & 7];
        for (int o = 4; o > 0; o >>= 1) s += __shfl_xor_sync(0xffffffff, s, o);
        if (lid == 0) red[0] = s;
    }
    __syncthreads();
    float inv = 1.0f / red[0];
#pragma unroll
    for (int i = 0; i < 8; i++) v[i] *= inv;
    r4[tid]       = make_float4(v[0], v[1], v[2], v[3]);
    r4[tid + 256] = make_float4(v[4], v[5], v[6], v[7]);
    long long rb = row * (long long)TT;
#pragma unroll
    for (int half = 0; half < 2; half++) {
        long long o = rb + half * 1024 + tid * 4;
        float p0 = v[half * 4 + 0], p1 = v[half * 4 + 1];
        float p2 = v[half * 4 + 2], p3 = v[half * 4 + 3];
        __nv_bfloat162 h01 = __floats2bfloat162_rn(p0, p1);
        __nv_bfloat162 h23 = __floats2bfloat162_rn(p2, p3);
        float2 f01 = __bfloat1622float2(h01);
        float2 f23 = __bfloat1622float2(h23);
        __nv_bfloat162 l01 = __floats2bfloat162_rn(p0 - f01.x, p1 - f01.y);
        __nv_bfloat162 l23 = __floats2bfloat162_rn(p2 - f23.x, p3 - f23.y);
        uint2 hv, lv;
        hv.x = *(uint32_t*)&h01; hv.y = *(uint32_t*)&h23;
        lv.x = *(uint32_t*)&l01; lv.y = *(uint32_t*)&l23;
        *(uint2*)(ahi + o) = hv;
        *(uint2*)(alo + o) = lv;
    }
}

// =====================================================================
// Split-bf16 GEMM on mma.sync (HMMA).  C = alpha * A@B^T.
// A [M,K] hi/lo, B [N,K] hi/lo, both K-major bf16.
// Accumulates Ahi*Bhi + Alo*Bhi + Ahi*Blo in fp32 registers.
// 256 threads, tile 128 x BN, BK=32 elems (64B rows, SW64 swizzle),
// cp.async double buffering -> 64KB stage => 2 CTAs/SM.
// Fused epilogue: bias / GELU / residual; outputs fp32 and/or hi-lo bf16.
// =====================================================================
template<int BN>
__global__ __launch_bounds__(256, 2)
void gemm_mma(const bf16* __restrict__ Ahi, const bf16* __restrict__ Alo,
              const bf16* __restrict__ Bhi, const bf16* __restrict__ Blo,
              int K, int lda, int ldb, int ldc,
              float alpha,
              const float* __restrict__ bias,
              const float* __restrict__ residual, int ldres,
              int doGelu,
              float* __restrict__ Cf,
              bf16* __restrict__ Chi, bf16* __restrict__ Clo,
              int hdiv,
              long long sAb, long long sAh,
              long long sBb, long long sBh,
              long long sCb, long long sCh) {
    constexpr int TILE_A = 128 * 64;         // bytes (128 rows x 32 bf16)
    constexpr int TILE_B = BN * 64;
    constexpr int STAGE  = 2 * TILE_A + 2 * TILE_B;
    constexpr int WGM = (BN == 128) ? 2 : 4;     // warp grid
    constexpr int WGN = (BN == 128) ? 4 : 2;
    constexpr int MT  = (128 / WGM) / 16;        // m16 tiles per warp (4 or 2)
    constexpr int NT  = (BN / WGN) / 8;          // n8 tiles per warp (4)

    extern __shared__ char smem[];
    const uint32_t sb = smem_to_u32(smem);

    const int tid  = threadIdx.x;
    const int warp = tid >> 5, lane = tid & 31;
    const int wm = warp / WGN, wn = warp % WGN;
    const int rw = wm * (128 / WGM);
    const int cw = wn * (BN / WGN);

    int z = blockIdx.z;
    int bbz = z / hdiv, hhz = z % hdiv;
    Ahi += bbz * sAb + hhz * sAh;  Alo += bbz * sAb + hhz * sAh;
    Bhi += bbz * sBb + hhz * sBh;  Blo += bbz * sBb + hhz * sBh;
    const long long coff = bbz * sCb + hhz * sCh;

    const int row0 = blockIdx.y * 128;
    const int col0 = blockIdx.x * BN;

    float acc[MT][NT][4];
#pragma unroll
    for (int i = 0; i < MT; i++)
#pragma unroll
        for (int j = 0; j < NT; j++)
#pragma unroll
            for (int q = 0; q < 4; q++) acc[i][j][q] = 0.f;

    const int nc = K >> 5;

    auto copy_chunk = [&](int k0, int buf) {
        uint32_t ah = sb + buf * STAGE;
        uint32_t al = ah + TILE_A;
        uint32_t bh = ah + 2 * TILE_A;
        uint32_t bl = bh + TILE_B;
#pragma unroll
        for (int l = 0; l < 2; l++) {
            int idx = tid + l * 256;
            int row = idx >> 2, seg = idx & 3;
            long long g = (long long)(row0 + row) * lda + k0 + seg * 8;
            uint32_t sw = SMEM_SWIZZLE_64B((uint32_t)(row * 64 + seg * 16));
            cp16(ah + sw, Ahi + g);
            cp16(al + sw, Alo + g);
        }
#pragma unroll
        for (int l = 0; l < BN / 64; l++) {
            int idx = tid + l * 256;
            int row = idx >> 2, seg = idx & 3;
            long long g = (long long)(col0 + row) * ldb + k0 + seg * 8;
            uint32_t sw = SMEM_SWIZZLE_64B((uint32_t)(row * 64 + seg * 16));
            cp16(bh + sw, Bhi + g);
            cp16(bl + sw, Blo + g);
        }
    };

    copy_chunk(0, 0);
    CP_COMMIT();

    const int lr = lane & 15;       // A ldmatrix row
    const int lk = lane >> 4;       // A ldmatrix k-half
    const int bnrow = (lane & 7) + ((lane >> 4) & 1) * 8;   // B ldmatrix n row
    const int bkh   = (lane >> 3) & 1;                      // B ldmatrix k-half

    for (int c = 0; c < nc; c++) {
        if (c + 1 < nc) {
            copy_chunk((c + 1) << 5, (c + 1) & 1);
            CP_COMMIT();
            CP_WAIT1();
        } else {
            CP_WAIT0();
        }
        __syncthreads();

        uint32_t abase = sb + (c & 1) * STAGE;
        uint32_t bbase = abase + 2 * TILE_A;
#pragma unroll
        for (int ks = 0; ks < 2; ks++) {
            uint32_t afh[MT][4], afl[MT][4];
#pragma unroll
            for (int mt = 0; mt < MT; mt++) {
                uint32_t off = SMEM_SWIZZLE_64B((uint32_t)((rw + mt * 16 + lr) * 64 + ks * 32 + lk * 16));
                ldsm_x4(afh[mt], abase + off);
                ldsm_x4(afl[mt], abase + TILE_A + off);
            }
            uint32_t bfh[NT][2], bfl[NT][2];
#pragma unroll
            for (int g = 0; g < NT / 2; g++) {
                uint32_t off = SMEM_SWIZZLE_64B((uint32_t)((cw + g * 16 + bnrow) * 64 + ks * 32 + bkh * 16));
                uint32_t r4[4];
                ldsm_x4(r4, bbase + off);
                bfh[2 * g][0] = r4[0]; bfh[2 * g][1] = r4[1];
                bfh[2 * g + 1][0] = r4[2]; bfh[2 * g + 1][1] = r4[3];
                ldsm_x4(r4, bbase + TILE_B + off);
                bfl[2 * g][0] = r4[0]; bfl[2 * g][1] = r4[1];
                bfl[2 * g + 1][0] = r4[2]; bfl[2 * g + 1][1] = r4[3];
            }
#pragma unroll
            for (int mt = 0; mt < MT; mt++)
#pragma unroll
                for (int nt = 0; nt < NT; nt++) {
                    mma16816(acc[mt][nt], afh[mt], bfh[nt]);
                    mma16816(acc[mt][nt], afl[mt], bfh[nt]);
                    mma16816(acc[mt][nt], afh[mt], bfl[nt]);
                }
        }
        __syncthreads();
    }

    // ---- epilogue: regs -> smem stage -> fused ops -> coalesced gmem ----
    constexpr int SP = BN + 4;                 // stage pitch (floats)
    float* stage = (float*)smem;
    {
        int qr = lane >> 2;
        int qc = (lane & 3) * 2;
#pragma unroll
        for (int mt = 0; mt < MT; mt++) {
            int r1 = rw + mt * 16 + qr;
            int r2 = r1 + 8;
#pragma unroll
            for (int nt = 0; nt < NT; nt++) {
                int cc = cw + nt * 8 + qc;
                stage[r1 * SP + cc]     = acc[mt][nt][0];
                stage[r1 * SP + cc + 1] = acc[mt][nt][1];
                stage[r2 * SP + cc]     = acc[mt][nt][2];
                stage[r2 * SP + cc + 1] = acc[mt][nt][3];
            }
        }
    }
    __syncthreads();
#pragma unroll
    for (int l = 0; l < BN / 8; l++) {
        int idx = tid + l * 256;
        int r2 = idx / (BN / 4);
        int c4 = (idx % (BN / 4)) * 4;
        int grow = row0 + r2;
        int gcol = col0 + c4;
        float4 v = *(float4*)&stage[r2 * SP + c4];
        float* vp = (float*)&v;
#pragma unroll
        for (int j = 0; j < 4; j++) {
            float x = vp[j] * alpha;
            if (bias) x += bias[gcol + j];
            if (doGelu) x = 0.5f * x * (1.0f + erff(x * 0.70710678118654752f));
            if (residual) x += residual[(long long)grow * ldres + gcol + j];
            vp[j] = x;
        }
        long long o = coff + (long long)grow * ldc + gcol;
        if (Cf) *(float4*)&Cf[o] = v;
        if (Chi) {
            __nv_bfloat162 h01 = __floats2bfloat162_rn(vp[0], vp[1]);
            __nv_bfloat162 h23 = __floats2bfloat162_rn(vp[2], vp[3]);
            float2 f01 = __bfloat1622float2(h01);
            float2 f23 = __bfloat1622float2(h23);
            __nv_bfloat162 l01 = __floats2bfloat162_rn(vp[0] - f01.x, vp[1] - f01.y);
            __nv_bfloat162 l23 = __floats2bfloat162_rn(vp[2] - f23.x, vp[3] - f23.y);
            uint2 hv, lv;
            hv.x = *(uint32_t*)&h01; hv.y = *(uint32_t*)&h23;
            lv.x = *(uint32_t*)&l01; lv.y = *(uint32_t*)&l23;
            *(uint2*)&Chi[o] = hv;
            *(uint2*)&Clo[o] = lv;
        }
    }
}

// ---------------- host side ----------------
// stage: 2*(2*8192 + 2*BN*64); epilogue: 128*(BN+4)*4 — take max
static const int SMEM128 = 128 * 132 * 4;     // 67584 (> 65536 stage)
static const int SMEM64  = 2 * (2 * 8192 + 2 * 4096);  // 49152 (> 34816 epi)

extern "C" void kernel_launch(void* const* d_in, const int* in_sizes, int n_in,
                              void* d_out, int out_size) {
    const float* X      = (const float*)d_in[0];
    const float* WQ     = (const float*)d_in[1];
    const float* WK     = (const float*)d_in[2];
    const float* WV     = (const float*)d_in[3];
    const float* WO     = (const float*)d_in[4];
    const float* attn_g = (const float*)d_in[5];
    const float* attn_b = (const float*)d_in[6];
    const float* ff_g   = (const float*)d_in[7];
    const float* ff_b   = (const float*)d_in[8];
    const float* fW1    = (const float*)d_in[9];
    const float* fb1    = (const float*)d_in[10];
    const float* fW2    = (const float*)d_in[11];
    const float* fb2    = (const float*)d_in[12];

    float* out0 = (float*)d_out;                         // [B,T,D]
    float* attn = out0 + (long long)ROWS * DD;           // [B,H,T,T]

    cudaFuncSetAttribute(gemm_mma<128>, cudaFuncAttributeMaxDynamicSharedMemorySize, SMEM128);
    cudaFuncSetAttribute(gemm_mma<64>,  cudaFuncAttributeMaxDynamicSharedMemorySize, SMEM64);

    bf16 *wqkvT_h, *wqkvT_l, *woT_h, *woT_l, *fw1T_h, *fw1T_l, *fw2T_h, *fw2T_l;
    bf16 *nx_h, *nx_l, *qkv_h, *qkv_l, *vt_h, *vt_l, *attn_h, *attn_l;
    bf16 *nv_h, *nv_l, *pre_h, *pre_l, *hid_h, *hid_l;
    float *ss, *pre;
    cudaGetSymbolAddress((void**)&wqkvT_h, g_wqkvT_h); cudaGetSymbolAddress((void**)&wqkvT_l, g_wqkvT_l);
    cudaGetSymbolAddress((void**)&woT_h,  g_woT_h);    cudaGetSymbolAddress((void**)&woT_l,  g_woT_l);
    cudaGetSymbolAddress((void**)&fw1T_h, g_fw1T_h);   cudaGetSymbolAddress((void**)&fw1T_l, g_fw1T_l);
    cudaGetSymbolAddress((void**)&fw2T_h, g_fw2T_h);   cudaGetSymbolAddress((void**)&fw2T_l, g_fw2T_l);
    cudaGetSymbolAddress((void**)&nx_h,   g_nx_h);     cudaGetSymbolAddress((void**)&nx_l,   g_nx_l);
    cudaGetSymbolAddress((void**)&qkv_h,  g_qkv_h);    cudaGetSymbolAddress((void**)&qkv_l,  g_qkv_l);
    cudaGetSymbolAddress((void**)&vt_h,   g_vt_h);     cudaGetSymbolAddress((void**)&vt_l,   g_vt_l);
    cudaGetSymbolAddress((void**)&attn_h, g_attn_h);   cudaGetSymbolAddress((void**)&attn_l, g_attn_l);
    cudaGetSymbolAddress((void**)&nv_h,   g_nv_h);     cudaGetSymbolAddress((void**)&nv_l,   g_nv_l);
    cudaGetSymbolAddress((void**)&pre_h,  g_pre_h);    cudaGetSymbolAddress((void**)&pre_l,  g_pre_l);
    cudaGetSymbolAddress((void**)&hid_h,  g_hid_h);    cudaGetSymbolAddress((void**)&hid_l,  g_hid_l);
    cudaGetSymbolAddress((void**)&ss,     g_ss);       cudaGetSymbolAddress((void**)&pre,    g_pre);

    dim3 tb32(32, 8);

    // 1. weight transposes + splits
    transpose_split<<<dim3(2, 32, 16), tb32>>>(WQ, wqkvT_h,                wqkvT_l,                64, DD, (long long)DD * PP, (long long)PP * DD);
    transpose_split<<<dim3(2, 32, 16), tb32>>>(WK, wqkvT_h + DD * DD,      wqkvT_l + DD * DD,      64, DD, (long long)DD * PP, (long long)PP * DD);
    transpose_split<<<dim3(2, 32, 16), tb32>>>(WV, wqkvT_h + 2 * DD * DD,  wqkvT_l + 2 * DD * DD,  64, DD, (long long)DD * PP, (long long)PP * DD);
    transpose_split<<<dim3(128, 32, 1), tb32>>>(fW1, fw1T_h, fw1T_l, FFD, DD, 0, 0);
    transpose_split<<<dim3(32, 128, 1), tb32>>>(fW2, fw2T_h, fw2T_l, DD, FFD, 0, 0);
    transpose_split<<<dim3(32, 32, 1),  tb32>>>(WO,  woT_h,  woT_l,  DD, DD, 0, 0);

    // 2. LN1 -> nx hi/lo
    ln_split_kernel<<<ROWS, 256>>>(X, attn_g, attn_b, nullptr, nullptr, nx_h, nx_l);

    // 3. QKV: [8192,1024] x [3072,1024]^T -> qkv hi/lo [8192,3072]
    gemm_mma<128><<<dim3(24, 64, 1), 256, SMEM128>>>(
        nx_h, nx_l, wqkvT_h, wqkvT_l, DD, DD, DD, 3 * DD,
        1.f, nullptr, nullptr, 0, 0, nullptr, qkv_h, qkv_l,
        1, 0, 0, 0, 0, 0, 0);

    // 4. V^T per head
    vt_kernel<<<dim3(2, 64, 64), tb32>>>(qkv_h, qkv_l, vt_h, vt_l);

    // 5. scores (faithful index swap): rows = K-tokens, cols = Q-tokens
    gemm_mma<128><<<dim3(16, 16, 64), 256, SMEM128>>>(
        qkv_h + DD, qkv_l + DD, qkv_h, qkv_l, PP, 3 * DD, 3 * DD, TT,
        0.125f, nullptr, nullptr, 0, 0, attn, nullptr, nullptr,
        16,
        (long long)TT * 3 * DD, PP,
        (long long)TT * 3 * DD, PP,
        16LL * TT * TT, (long long)TT * TT);

    // 6. softmax + split
    softmax_split_kernel<<<BBATCH * HH * TT, 256>>>(attn, attn_h, attn_l);

    // 7. AV: [T,T] x [P=64,T]^T -> nv hi/lo
    gemm_mma<64><<<dim3(1, 16, 64), 256, SMEM64>>>(
        attn_h, attn_l, vt_h, vt_l, TT, TT, TT, DD,
        1.f, nullptr, nullptr, 0, 0, nullptr, nv_h, nv_l,
        16,
        16LL * TT * TT, (long long)TT * TT,
        16LL * PP * TT, (long long)PP * TT,
        (long long)TT * DD, PP);

    // 8. WO: [8192,1024] x [1024,1024]^T -> ss fp32
    gemm_mma<128><<<dim3(8, 64, 1), 256, SMEM128>>>(
        nv_h, nv_l, woT_h, woT_l, DD, DD, DD, DD,
        1.f, nullptr, nullptr, 0, 0, ss, nullptr, nullptr,
        1, 0, 0, 0, 0, 0, 0);

    // 9. pre_ff = X + LN(ss): fp32 + hi/lo
    ln_split_kernel<<<ROWS, 256>>>(ss, ff_g, ff_b, X, pre, pre_h, pre_l);

    // 10. FF1 + bias + gelu -> hid hi/lo
    gemm_mma<128><<<dim3(32, 64, 1), 256, SMEM128>>>(
        pre_h, pre_l, fw1T_h, fw1T_l, DD, DD, DD, FFD,
        1.f, fb1, nullptr, 0, 1, nullptr, hid_h, hid_l,
        1, 0, 0, 0, 0, 0, 0);

    // 11. FF2 + bias + residual(pre) -> out0 fp32
    gemm_mma<128><<<dim3(8, 64, 1), 256, SMEM128>>>(
        hid_h, hid_l, fw2T_h, fw2T_l, FFD, FFD, FFD, DD,
        1.f, fb2, pre, DD, 0, out0, nullptr, nullptr,
        1, 0, 0, 0, 0, 0, 0);
}

// round 9
// speedup vs baseline: 5.5537x; 1.0270x over previous
#include <cuda_runtime.h>
#include <cuda_bf16.h>
#include <cstdint>
#include <math.h>

// ---------------- problem constants ----------------
#define BBATCH 4
#define TT 2048
#define DD 1024
#define HH 16
#define PP 64
#define FFD 4096
#define ROWS (BBATCH*TT)          // 8192

typedef __nv_bfloat16 bf16;

#define SMEM_SWIZZLE_64B(off)  ((off) ^ (((off) >> 3) & 0x30))

__device__ __forceinline__ uint32_t smem_to_u32(const void* p) {
    uint32_t a;
    asm("{ .reg .u64 t; cvta.to.shared.u64 t, %1; cvt.u32.u64 %0, t; }" : "=r"(a) : "l"(p));
    return a;
}
__device__ __forceinline__ void cp16(uint32_t s, const void* g) {
    asm volatile("cp.async.cg.shared.global [%0], [%1], 16;" :: "r"(s), "l"(g));
}
#define CP_COMMIT() asm volatile("cp.async.commit_group;" ::: "memory")
#define CP_WAIT1()  asm volatile("cp.async.wait_group 1;" ::: "memory")

__device__ __forceinline__ void ldsm_x4(uint32_t* r, uint32_t addr) {
    asm volatile("ldmatrix.sync.aligned.m8n8.x4.shared.b16 {%0,%1,%2,%3}, [%4];"
                 : "=r"(r[0]), "=r"(r[1]), "=r"(r[2]), "=r"(r[3]) : "r"(addr));
}
__device__ __forceinline__ void mma16816(float* c, const uint32_t* a, const uint32_t* b) {
    asm volatile("mma.sync.aligned.m16n8k16.row.col.f32.bf16.bf16.f32 "
                 "{%0,%1,%2,%3}, {%4,%5,%6,%7}, {%8,%9}, {%0,%1,%2,%3};"
                 : "+f"(c[0]), "+f"(c[1]), "+f"(c[2]), "+f"(c[3])
                 : "r"(a[0]), "r"(a[1]), "r"(a[2]), "r"(a[3]), "r"(b[0]), "r"(b[1]));
}

// ---------------- scratch (static __device__, no allocation) ----------------
static __device__ bf16 g_wqkvT_h[3 * DD * DD], g_wqkvT_l[3 * DD * DD];     // [3072,1024]
static __device__ bf16 g_woT_h[DD * DD],       g_woT_l[DD * DD];           // [1024,1024]
static __device__ bf16 g_fw1T_h[FFD * DD],     g_fw1T_l[FFD * DD];         // [4096,1024]
static __device__ bf16 g_fw2T_h[DD * FFD],     g_fw2T_l[DD * FFD];         // [1024,4096]
static __device__ bf16 g_nx_h[ROWS * DD],      g_nx_l[ROWS * DD];
static __device__ bf16 g_qkv_h[ROWS * 3 * DD], g_qkv_l[ROWS * 3 * DD];
static __device__ bf16 g_vt_h[(size_t)BBATCH * HH * PP * TT], g_vt_l[(size_t)BBATCH * HH * PP * TT];
static __device__ bf16 g_attn_h[(size_t)BBATCH * HH * TT * TT];
static __device__ bf16 g_nv_h[ROWS * DD],      g_nv_l[ROWS * DD];
static __device__ bf16 g_pre_h[ROWS * DD],     g_pre_l[ROWS * DD];
static __device__ bf16 g_hid_h[(size_t)ROWS * FFD], g_hid_l[(size_t)ROWS * FFD];
static __device__ float g_ss [ROWS * DD];
static __device__ float g_pre[ROWS * DD];

// ---------------- transpose + split: fp32 in [R,C] -> bf16 hi/lo [C,R] ----------------
__global__ void transpose_split(const float* __restrict__ in,
                                bf16* __restrict__ ohi, bf16* __restrict__ olo,
                                int ldin, int ldout, long long sIn, long long sOut) {
    __shared__ float t[32][33];
    const float* ip = in + (long long)blockIdx.z * sIn;
    long long ob = (long long)blockIdx.z * sOut;
    int r0 = blockIdx.y * 32, c0 = blockIdx.x * 32;
    int tx = threadIdx.x, ty = threadIdx.y;
#pragma unroll
    for (int j = 0; j < 32; j += 8)
        t[ty + j][tx] = ip[(long long)(r0 + ty + j) * ldin + c0 + tx];
    __syncthreads();
#pragma unroll
    for (int j = 0; j < 32; j += 8) {
        float v = t[tx][ty + j];
        bf16 h = __float2bfloat16(v);
        long long o = ob + (long long)(c0 + ty + j) * ldout + r0 + tx;
        ohi[o] = h;
        olo[o] = __float2bfloat16(v - __bfloat162float(h));
    }
}

// ---------------- V^T extraction (bf16 -> bf16 transpose per head) ----------------
__global__ void vt_kernel(const bf16* __restrict__ qhi, const bf16* __restrict__ qlo,
                          bf16* __restrict__ vhi, bf16* __restrict__ vlo) {
    __shared__ bf16 th[32][33], tl[32][33];
    int z = blockIdx.z, bb = z >> 4, hh = z & 15;
    const long long ib = (long long)bb * TT * (3 * DD) + 2 * DD + hh * PP;
    const long long ob = (long long)z * PP * TT;
    int t0 = blockIdx.y * 32, p0 = blockIdx.x * 32;
    int tx = threadIdx.x, ty = threadIdx.y;
#pragma unroll
    for (int j = 0; j < 32; j += 8) {
        long long g = ib + (long long)(t0 + ty + j) * (3 * DD) + p0 + tx;
        th[ty + j][tx] = qhi[g];
        tl[ty + j][tx] = qlo[g];
    }
    __syncthreads();
#pragma unroll
    for (int j = 0; j < 32; j += 8) {
        long long o = ob + (long long)(p0 + ty + j) * TT + t0 + tx;
        vhi[o] = th[tx][ty + j];
        vlo[o] = tl[tx][ty + j];
    }
}

// ---------------- layernorm (+opt residual), float4 path ----------------
__global__ void ln_split_kernel(const float* __restrict__ x,
                                const float* __restrict__ gamma,
                                const float* __restrict__ beta,
                                const float* __restrict__ residual,
                                float* __restrict__ outf,
                                bf16* __restrict__ ohi, bf16* __restrict__ olo) {
    int row = blockIdx.x;
    int tid = threadIdx.x;               // 256 threads, 4 contiguous elems each
    long long rb = (long long)row * DD;
    float4 v = *(const float4*)(x + rb + tid * 4);
    float s  = v.x + v.y + v.z + v.w;
    float sq = v.x * v.x + v.y * v.y + v.z * v.z + v.w * v.w;
    __shared__ float red[2][32];
    for (int o = 16; o > 0; o >>= 1) {
        s  += __shfl_xor_sync(0xffffffff, s, o);
        sq += __shfl_xor_sync(0xffffffff, sq, o);
    }
    int wid = tid >> 5, lid = tid & 31;
    if (lid == 0) { red[0][wid] = s; red[1][wid] = sq; }
    __syncthreads();
    if (wid == 0) {
        s = red[0][lid & 7]; sq = red[1][lid & 7];
        for (int o = 4; o > 0; o >>= 1) {
            s  += __shfl_xor_sync(0xffffffff, s, o);
            sq += __shfl_xor_sync(0xffffffff, sq, o);
        }
        if (lid == 0) { red[0][0] = s; red[1][0] = sq; }
    }
    __syncthreads();
    float mean = red[0][0] * (1.0f / DD);
    float var  = red[1][0] * (1.0f / DD) - mean * mean;
    float rstd = rsqrtf(var + 1e-5f);
    float4 gm = *(const float4*)(gamma + tid * 4);
    float4 bt = *(const float4*)(beta  + tid * 4);
    float o0 = (v.x - mean) * rstd * gm.x + bt.x;
    float o1 = (v.y - mean) * rstd * gm.y + bt.y;
    float o2 = (v.z - mean) * rstd * gm.z + bt.z;
    float o3 = (v.w - mean) * rstd * gm.w + bt.w;
    if (residual) {
        float4 rr = *(const float4*)(residual + rb + tid * 4);
        o0 += rr.x; o1 += rr.y; o2 += rr.z; o3 += rr.w;
    }
    if (outf) {
        float4 ov = make_float4(o0, o1, o2, o3);
        *(float4*)(outf + rb + tid * 4) = ov;
    }
    __nv_bfloat162 h01 = __floats2bfloat162_rn(o0, o1);
    __nv_bfloat162 h23 = __floats2bfloat162_rn(o2, o3);
    float2 f01 = __bfloat1622float2(h01);
    float2 f23 = __bfloat1622float2(h23);
    __nv_bfloat162 l01 = __floats2bfloat162_rn(o0 - f01.x, o1 - f01.y);
    __nv_bfloat162 l23 = __floats2bfloat162_rn(o2 - f23.x, o3 - f23.y);
    uint2 hv, lv;
    hv.x = *(uint32_t*)&h01; hv.y = *(uint32_t*)&h23;
    lv.x = *(uint32_t*)&l01; lv.y = *(uint32_t*)&l23;
    *(uint2*)(ohi + rb + tid * 4) = hv;
    *(uint2*)(olo + rb + tid * 4) = lv;
}

// ---------------- softmax over last dim + hi-only split output ----------------
__global__ void softmax_split_kernel(float* __restrict__ a,
                                     bf16* __restrict__ ahi) {
    long long row = blockIdx.x;
    float4* r4 = (float4*)(a + row * (long long)TT);
    int tid = threadIdx.x;               // 256 threads, 2 float4 each
    float4 va = r4[tid], vb = r4[tid + 256];
    float v[8] = {va.x, va.y, va.z, va.w, vb.x, vb.y, vb.z, vb.w};
    float mx = -1e30f;
#pragma unroll
    for (int i = 0; i < 8; i++) mx = fmaxf(mx, v[i]);
    __shared__ float red[32];
    for (int o = 16; o > 0; o >>= 1) mx = fmaxf(mx, __shfl_xor_sync(0xffffffff, mx, o));
    int wid = tid >> 5, lid = tid & 31;
    if (lid == 0) red[wid] = mx;
    __syncthreads();
    if (wid == 0) {
        mx = red[lid & 7];
        for (int o = 4; o > 0; o >>= 1) mx = fmaxf(mx, __shfl_xor_sync(0xffffffff, mx, o));
        if (lid == 0) red[0] = mx;
    }
    __syncthreads();
    mx = red[0];
    float s = 0.f;
#pragma unroll
    for (int i = 0; i < 8; i++) { v[i] = __expf(v[i] - mx); s += v[i]; }
    __syncthreads();
    for (int o = 16; o > 0; o >>= 1) s += __shfl_xor_sync(0xffffffff, s, o);
    if (lid == 0) red[wid] = s;
    __syncthreads();
    if (wid == 0) {
        s = red[lid & 7];
        for (int o = 4; o > 0; o >>= 1) s += __shfl_xor_sync(0xffffffff, s, o);
        if (lid == 0) red[0] = s;
    }
    __syncthreads();
    float inv = 1.0f / red[0];
#pragma unroll
    for (int i = 0; i < 8; i++) v[i] *= inv;
    r4[tid]       = make_float4(v[0], v[1], v[2], v[3]);
    r4[tid + 256] = make_float4(v[4], v[5], v[6], v[7]);
    long long rb = row * (long long)TT;
#pragma unroll
    for (int half = 0; half < 2; half++) {
        long long o = rb + half * 1024 + tid * 4;
        __nv_bfloat162 h01 = __floats2bfloat162_rn(v[half * 4 + 0], v[half * 4 + 1]);
        __nv_bfloat162 h23 = __floats2bfloat162_rn(v[half * 4 + 2], v[half * 4 + 3]);
        uint2 hv;
        hv.x = *(uint32_t*)&h01; hv.y = *(uint32_t*)&h23;
        *(uint2*)(ahi + o) = hv;
    }
}

// =====================================================================
// Split-bf16 GEMM on mma.sync (HMMA).  C = alpha * A@B^T.
// A [M,K] hi(/lo if ALO), B [N,K] hi/lo, K-major bf16.
// Passes: Ahi*Bhi (+ Alo*Bhi if ALO) + Ahi*Blo, fp32 accum.
// 256 threads, tile 128 x BN, BK=32 (64B rows, SW64 swizzle),
// 3-stage cp.async pipeline; 2 CTAs/SM.
// Fused epilogue: bias / GELU / residual; fp32 and/or hi-lo bf16 out.
// =====================================================================
template<int BN, bool ALO>
__global__ __launch_bounds__(256, 2)
void gemm_mma(const bf16* __restrict__ Ahi, const bf16* __restrict__ Alo,
              const bf16* __restrict__ Bhi, const bf16* __restrict__ Blo,
              int K, int lda, int ldb, int ldc,
              float alpha,
              const float* __restrict__ bias,
              const float* __restrict__ residual, int ldres,
              int doGelu,
              float* __restrict__ Cf,
              bf16* __restrict__ Chi, bf16* __restrict__ Clo,
              int hdiv,
              long long sAb, long long sAh,
              long long sBb, long long sBh,
              long long sCb, long long sCh) {
    constexpr int NA = ALO ? 2 : 1;
    constexpr int TILE_A = 128 * 64;         // bytes per A operand (128 rows x 32 bf16)
    constexpr int TILE_B = BN * 64;
    constexpr int STAGE  = NA * TILE_A + 2 * TILE_B;
    constexpr int WGM = (BN == 128) ? 2 : 4;     // warp grid
    constexpr int WGN = (BN == 128) ? 4 : 2;
    constexpr int MT  = (128 / WGM) / 16;        // m16 tiles per warp
    constexpr int NT  = (BN / WGN) / 8;          // n8 tiles per warp

    extern __shared__ char smem[];
    const uint32_t sb = smem_to_u32(smem);

    const int tid  = threadIdx.x;
    const int warp = tid >> 5, lane = tid & 31;
    const int wm = warp / WGN, wn = warp % WGN;
    const int rw = wm * (128 / WGM);
    const int cw = wn * (BN / WGN);

    int z = blockIdx.z;
    int bbz = z / hdiv, hhz = z % hdiv;
    Ahi += bbz * sAb + hhz * sAh;
    if (ALO) Alo += bbz * sAb + hhz * sAh;
    Bhi += bbz * sBb + hhz * sBh;  Blo += bbz * sBb + hhz * sBh;
    const long long coff = bbz * sCb + hhz * sCh;

    const int row0 = blockIdx.y * 128;
    const int col0 = blockIdx.x * BN;

    float acc[MT][NT][4];
#pragma unroll
    for (int i = 0; i < MT; i++)
#pragma unroll
        for (int j = 0; j < NT; j++)
#pragma unroll
            for (int q = 0; q < 4; q++) acc[i][j][q] = 0.f;

    const int nc = K >> 5;

    auto copy_chunk = [&](int k0, int buf) {
        uint32_t ah = sb + buf * STAGE;
        uint32_t bh = ah + NA * TILE_A;
        uint32_t bl = bh + TILE_B;
#pragma unroll
        for (int l = 0; l < 2; l++) {
            int idx = tid + l * 256;
            int row = idx >> 2, seg = idx & 3;
            long long g = (long long)(row0 + row) * lda + k0 + seg * 8;
            uint32_t sw = SMEM_SWIZZLE_64B((uint32_t)(row * 64 + seg * 16));
            cp16(ah + sw, Ahi + g);
            if (ALO) cp16(ah + TILE_A + sw, Alo + g);
        }
#pragma unroll
        for (int l = 0; l < BN / 64; l++) {
            int idx = tid + l * 256;
            int row = idx >> 2, seg = idx & 3;
            long long g = (long long)(col0 + row) * ldb + k0 + seg * 8;
            uint32_t sw = SMEM_SWIZZLE_64B((uint32_t)(row * 64 + seg * 16));
            cp16(bh + sw, Bhi + g);
            cp16(bl + sw, Blo + g);
        }
    };

    // 3-stage prologue: chunks 0 and 1 in flight
    copy_chunk(0, 0);
    CP_COMMIT();
    if (nc > 1) copy_chunk(32, 1);
    CP_COMMIT();

    const int lr = lane & 15;       // A ldmatrix row
    const int lk = lane >> 4;       // A ldmatrix k-half
    const int bnrow = (lane & 7) + ((lane >> 4) & 1) * 8;   // B ldmatrix n row
    const int bkh   = (lane >> 3) & 1;                      // B ldmatrix k-half

    for (int c = 0; c < nc; c++) {
        CP_WAIT1();                 // chunk c landed (c+1 may be in flight)
        __syncthreads();
        // issue chunk c+2 into buffer (c+2)%3 (== (c-1)%3, already consumed)
        if (c + 2 < nc) copy_chunk((c + 2) << 5, (c + 2) % 3);
        CP_COMMIT();                // always commit to keep group counting aligned

        uint32_t abase = sb + (c % 3) * STAGE;
        uint32_t bbase = abase + NA * TILE_A;
#pragma unroll
        for (int ks = 0; ks < 2; ks++) {
            uint32_t afh[MT][4], afl[MT][4];
#pragma unroll
            for (int mt = 0; mt < MT; mt++) {
                uint32_t off = SMEM_SWIZZLE_64B((uint32_t)((rw + mt * 16 + lr) * 64 + ks * 32 + lk * 16));
                ldsm_x4(afh[mt], abase + off);
                if (ALO) ldsm_x4(afl[mt], abase + TILE_A + off);
            }
            uint32_t bfh[NT][2], bfl[NT][2];
#pragma unroll
            for (int g = 0; g < NT / 2; g++) {
                uint32_t off = SMEM_SWIZZLE_64B((uint32_t)((cw + g * 16 + bnrow) * 64 + ks * 32 + bkh * 16));
                uint32_t r4[4];
                ldsm_x4(r4, bbase + off);
                bfh[2 * g][0] = r4[0]; bfh[2 * g][1] = r4[1];
                bfh[2 * g + 1][0] = r4[2]; bfh[2 * g + 1][1] = r4[3];
                ldsm_x4(r4, bbase + TILE_B + off);
                bfl[2 * g][0] = r4[0]; bfl[2 * g][1] = r4[1];
                bfl[2 * g + 1][0] = r4[2]; bfl[2 * g + 1][1] = r4[3];
            }
#pragma unroll
            for (int mt = 0; mt < MT; mt++)
#pragma unroll
                for (int nt = 0; nt < NT; nt++) {
                    mma16816(acc[mt][nt], afh[mt], bfh[nt]);
                    if (ALO) mma16816(acc[mt][nt], afl[mt], bfh[nt]);
                    mma16816(acc[mt][nt], afh[mt], bfl[nt]);
                }
        }
    }
    __syncthreads();   // all warps done with mainloop smem before staging

    // ---- epilogue: regs -> smem stage -> fused ops -> coalesced gmem ----
    constexpr int SP = BN + 4;                 // stage pitch (floats)
    float* stage = (float*)smem;
    {
        int qr = lane >> 2;
        int qc = (lane & 3) * 2;
#pragma unroll
        for (int mt = 0; mt < MT; mt++) {
            int r1 = rw + mt * 16 + qr;
            int r2 = r1 + 8;
#pragma unroll
            for (int nt = 0; nt < NT; nt++) {
                int cc = cw + nt * 8 + qc;
                stage[r1 * SP + cc]     = acc[mt][nt][0];
                stage[r1 * SP + cc + 1] = acc[mt][nt][1];
                stage[r2 * SP + cc]     = acc[mt][nt][2];
                stage[r2 * SP + cc + 1] = acc[mt][nt][3];
            }
        }
    }
    __syncthreads();
#pragma unroll
    for (int l = 0; l < BN / 8; l++) {
        int idx = tid + l * 256;
        int r2 = idx / (BN / 4);
        int c4 = (idx % (BN / 4)) * 4;
        int grow = row0 + r2;
        int gcol = col0 + c4;
        float4 v = *(float4*)&stage[r2 * SP + c4];
        float* vp = (float*)&v;
#pragma unroll
        for (int j = 0; j < 4; j++) {
            float x = vp[j] * alpha;
            if (bias) x += bias[gcol + j];
            if (doGelu) x = 0.5f * x * (1.0f + erff(x * 0.70710678118654752f));
            if (residual) x += residual[(long long)grow * ldres + gcol + j];
            vp[j] = x;
        }
        long long o = coff + (long long)grow * ldc + gcol;
        if (Cf) *(float4*)&Cf[o] = v;
        if (Chi) {
            __nv_bfloat162 h01 = __floats2bfloat162_rn(vp[0], vp[1]);
            __nv_bfloat162 h23 = __floats2bfloat162_rn(vp[2], vp[3]);
            float2 f01 = __bfloat1622float2(h01);
            float2 f23 = __bfloat1622float2(h23);
            __nv_bfloat162 l01 = __floats2bfloat162_rn(vp[0] - f01.x, vp[1] - f01.y);
            __nv_bfloat162 l23 = __floats2bfloat162_rn(vp[2] - f23.x, vp[3] - f23.y);
            uint2 hv, lv;
            hv.x = *(uint32_t*)&h01; hv.y = *(uint32_t*)&h23;
            lv.x = *(uint32_t*)&l01; lv.y = *(uint32_t*)&l23;
            *(uint2*)&Chi[o] = hv;
            *(uint2*)&Clo[o] = lv;
        }
    }
}

// ---------------- host side ----------------
// BN=128,ALO: 3 stages x (2*8192+2*8192)=98304; epi 128*132*4=67584 -> 98304
// BN=64,!ALO: 3 stages x (8192+2*4096)=49152;  epi 128*68*4=34816  -> 49152
static const int SMEM128 = 98304;
static const int SMEM64  = 49152;

extern "C" void kernel_launch(void* const* d_in, const int* in_sizes, int n_in,
                              void* d_out, int out_size) {
    const float* X      = (const float*)d_in[0];
    const float* WQ     = (const float*)d_in[1];
    const float* WK     = (const float*)d_in[2];
    const float* WV     = (const float*)d_in[3];
    const float* WO     = (const float*)d_in[4];
    const float* attn_g = (const float*)d_in[5];
    const float* attn_b = (const float*)d_in[6];
    const float* ff_g   = (const float*)d_in[7];
    const float* ff_b   = (const float*)d_in[8];
    const float* fW1    = (const float*)d_in[9];
    const float* fb1    = (const float*)d_in[10];
    const float* fW2    = (const float*)d_in[11];
    const float* fb2    = (const float*)d_in[12];

    float* out0 = (float*)d_out;                         // [B,T,D]
    float* attn = out0 + (long long)ROWS * DD;           // [B,H,T,T]

    cudaFuncSetAttribute(gemm_mma<128, true>, cudaFuncAttributeMaxDynamicSharedMemorySize, SMEM128);
    cudaFuncSetAttribute(gemm_mma<64, false>, cudaFuncAttributeMaxDynamicSharedMemorySize, SMEM64);

    bf16 *wqkvT_h, *wqkvT_l, *woT_h, *woT_l, *fw1T_h, *fw1T_l, *fw2T_h, *fw2T_l;
    bf16 *nx_h, *nx_l, *qkv_h, *qkv_l, *vt_h, *vt_l, *attn_h;
    bf16 *nv_h, *nv_l, *pre_h, *pre_l, *hid_h, *hid_l;
    float *ss, *pre;
    cudaGetSymbolAddress((void**)&wqkvT_h, g_wqkvT_h); cudaGetSymbolAddress((void**)&wqkvT_l, g_wqkvT_l);
    cudaGetSymbolAddress((void**)&woT_h,  g_woT_h);    cudaGetSymbolAddress((void**)&woT_l,  g_woT_l);
    cudaGetSymbolAddress((void**)&fw1T_h, g_fw1T_h);   cudaGetSymbolAddress((void**)&fw1T_l, g_fw1T_l);
    cudaGetSymbolAddress((void**)&fw2T_h, g_fw2T_h);   cudaGetSymbolAddress((void**)&fw2T_l, g_fw2T_l);
    cudaGetSymbolAddress((void**)&nx_h,   g_nx_h);     cudaGetSymbolAddress((void**)&nx_l,   g_nx_l);
    cudaGetSymbolAddress((void**)&qkv_h,  g_qkv_h);    cudaGetSymbolAddress((void**)&qkv_l,  g_qkv_l);
    cudaGetSymbolAddress((void**)&vt_h,   g_vt_h);     cudaGetSymbolAddress((void**)&vt_l,   g_vt_l);
    cudaGetSymbolAddress((void**)&attn_h, g_attn_h);
    cudaGetSymbolAddress((void**)&nv_h,   g_nv_h);     cudaGetSymbolAddress((void**)&nv_l,   g_nv_l);
    cudaGetSymbolAddress((void**)&pre_h,  g_pre_h);    cudaGetSymbolAddress((void**)&pre_l,  g_pre_l);
    cudaGetSymbolAddress((void**)&hid_h,  g_hid_h);    cudaGetSymbolAddress((void**)&hid_l,  g_hid_l);
    cudaGetSymbolAddress((void**)&ss,     g_ss);       cudaGetSymbolAddress((void**)&pre,    g_pre);

    dim3 tb32(32, 8);

    // 1. weight transposes + splits
    transpose_split<<<dim3(2, 32, 16), tb32>>>(WQ, wqkvT_h,                wqkvT_l,                64, DD, (long long)DD * PP, (long long)PP * DD);
    transpose_split<<<dim3(2, 32, 16), tb32>>>(WK, wqkvT_h + DD * DD,      wqkvT_l + DD * DD,      64, DD, (long long)DD * PP, (long long)PP * DD);
    transpose_split<<<dim3(2, 32, 16), tb32>>>(WV, wqkvT_h + 2 * DD * DD,  wqkvT_l + 2 * DD * DD,  64, DD, (long long)DD * PP, (long long)PP * DD);
    transpose_split<<<dim3(128, 32, 1), tb32>>>(fW1, fw1T_h, fw1T_l, FFD, DD, 0, 0);
    transpose_split<<<dim3(32, 128, 1), tb32>>>(fW2, fw2T_h, fw2T_l, DD, FFD, 0, 0);
    transpose_split<<<dim3(32, 32, 1),  tb32>>>(WO,  woT_h,  woT_l,  DD, DD, 0, 0);

    // 2. LN1 -> nx hi/lo
    ln_split_kernel<<<ROWS, 256>>>(X, attn_g, attn_b, nullptr, nullptr, nx_h, nx_l);

    // 3. QKV: [8192,1024] x [3072,1024]^T -> qkv hi/lo [8192,3072]
    gemm_mma<128, true><<<dim3(24, 64, 1), 256, SMEM128>>>(
        nx_h, nx_l, wqkvT_h, wqkvT_l, DD, DD, DD, 3 * DD,
        1.f, nullptr, nullptr, 0, 0, nullptr, qkv_h, qkv_l,
        1, 0, 0, 0, 0, 0, 0);

    // 4. V^T per head
    vt_kernel<<<dim3(2, 64, 64), tb32>>>(qkv_h, qkv_l, vt_h, vt_l);

    // 5. scores (faithful index swap): rows = K-tokens, cols = Q-tokens
    gemm_mma<128, true><<<dim3(16, 16, 64), 256, SMEM128>>>(
        qkv_h + DD, qkv_l + DD, qkv_h, qkv_l, PP, 3 * DD, 3 * DD, TT,
        0.125f, nullptr, nullptr, 0, 0, attn, nullptr, nullptr,
        16,
        (long long)TT * 3 * DD, PP,
        (long long)TT * 3 * DD, PP,
        16LL * TT * TT, (long long)TT * TT);

    // 6. softmax + hi-only split
    softmax_split_kernel<<<BBATCH * HH * TT, 256>>>(attn, attn_h);

    // 7. AV: [T,T](hi only) x [P=64,T]^T -> nv hi/lo
    gemm_mma<64, false><<<dim3(1, 16, 64), 256, SMEM64>>>(
        attn_h, nullptr, vt_h, vt_l, TT, TT, TT, DD,
        1.f, nullptr, nullptr, 0, 0, nullptr, nv_h, nv_l,
        16,
        16LL * TT * TT, (long long)TT * TT,
        16LL * PP * TT, (long long)PP * TT,
        (long long)TT * DD, PP);

    // 8. WO: [8192,1024] x [1024,1024]^T -> ss fp32
    gemm_mma<128, true><<<dim3(8, 64, 1), 256, SMEM128>>>(
        nv_h, nv_l, woT_h, woT_l, DD, DD, DD, DD,
        1.f, nullptr, nullptr, 0, 0, ss, nullptr, nullptr,
        1, 0, 0, 0, 0, 0, 0);

    // 9. pre_ff = X + LN(ss): fp32 + hi/lo
    ln_split_kernel<<<ROWS, 256>>>(ss, ff_g, ff_b, X, pre, pre_h, pre_l);

    // 10. FF1 + bias + gelu -> hid hi/lo
    gemm_mma<128, true><<<dim3(32, 64, 1), 256, SMEM128>>>(
        pre_h, pre_l, fw1T_h, fw1T_l, DD, DD, DD, FFD,
        1.f, fb1, nullptr, 0, 1, nullptr, hid_h, hid_l,
        1, 0, 0, 0, 0, 0, 0);

    // 11. FF2 + bias + residual(pre) -> out0 fp32
    gemm_mma<128, true><<<dim3(8, 64, 1), 256, SMEM128>>>(
        hid_h, hid_l, fw2T_h, fw2T_l, FFD, FFD, FFD, DD,
        1.f, fb2, pre, DD, 0, out0, nullptr, nullptr,
        1, 0, 0, 0, 0, 0, 0);
}